// round 2
// baseline (speedup 1.0000x reference)
#include <cuda_runtime.h>
#include <math.h>
#include <stdint.h>

// ---------------- scratch (device globals; no allocation) ----------------
#define MTOK (8192)          // B*N
#define DMODEL 256
#define HID 1024

__device__ float g_X[MTOK*DMODEL];      // mnt output / next input
__device__ float g_T[MTOK*DMODEL];      // temp
__device__ float g_H[MTOK*DMODEL];      // idt (post LN+pos)
__device__ float g_G[MTOK*HID];         // ff hidden
__device__ float g_F[MTOK*DMODEL];      // ff out
__device__ float g_QKV[MTOK*3*DMODEL];
__device__ float g_AO[MTOK*DMODEL];
__device__ float g_POS[512*DMODEL];
__device__ float g_BNP[2*128*DMODEL];   // partial sums / sumsq
__device__ float g_BNS[2*DMODEL];       // scale / shift
__device__ float g_PF[16*327680];       // pyramid flat [B][L*65536 + c*512 + n]
__device__ float g_FP[160*16*128];      // fcl partials
__device__ float g_ADD[16*128];

// ---------------- helpers ----------------
__device__ __forceinline__ float gelu_tanh(float x) {
    float x3 = x*x*x;
    return 0.5f*x*(1.f + tanhf(0.7978845608028654f*(x + 0.044715f*x3)));
}

// ---------------- positional table ----------------
__global__ void pos_k(float* __restrict__ pos) {
    int idx = blockIdx.x*256 + threadIdx.x;
    if (idx >= 512*256) return;
    int n = idx >> 8, d = idx & 255;
    double ang = (double)n / pow(10000.0, (double)(2*(d>>1)) / 256.0);
    pos[idx] = (float)((d & 1) ? cos(ang) : sin(ang));
}

// ---------------- GEMM: C[M,Nc] = A[M,K] @ W[K,Nc] + bias (+epilogue) ------
// tiles 128x128x16, 256 threads, 8x8 microtile
#define E_NONE 0
#define E_GELU 1
#define E_ADD  2
#define E_PYR  3

template<int EPI>
__global__ __launch_bounds__(256) void gemm_k(
    const float* __restrict__ A, const float* __restrict__ W,
    const float* __restrict__ bias, const float* __restrict__ R,
    float* __restrict__ C, int M, int Nc, int K, int pyr_base)
{
    __shared__ float As[16][132];
    __shared__ float Ws[16][128];
    int t = threadIdx.x;
    int bm = blockIdx.y * 128;
    int bn = blockIdx.x * 128;
    int ty = t >> 4, tx = t & 15;

    float acc[8][8];
    #pragma unroll
    for (int i = 0; i < 8; i++)
        #pragma unroll
        for (int j = 0; j < 8; j++) acc[i][j] = 0.f;

    int aRow = t >> 2;            // 0..63
    int aK   = (t & 3) * 4;       // 0,4,8,12
    int wN   = (t & 31) * 4;      // 0..124
    int wK   = t >> 5;            // 0..7

    for (int k0 = 0; k0 < K; k0 += 16) {
        float4 a0 = *(const float4*)&A[(size_t)(bm + aRow)*K + k0 + aK];
        float4 a1 = *(const float4*)&A[(size_t)(bm + aRow + 64)*K + k0 + aK];
        float4 w0 = *(const float4*)&W[(size_t)(k0 + wK)*Nc + bn + wN];
        float4 w1 = *(const float4*)&W[(size_t)(k0 + wK + 8)*Nc + bn + wN];
        As[aK+0][aRow] = a0.x; As[aK+1][aRow] = a0.y;
        As[aK+2][aRow] = a0.z; As[aK+3][aRow] = a0.w;
        As[aK+0][aRow+64] = a1.x; As[aK+1][aRow+64] = a1.y;
        As[aK+2][aRow+64] = a1.z; As[aK+3][aRow+64] = a1.w;
        *(float4*)&Ws[wK][wN]   = w0;
        *(float4*)&Ws[wK+8][wN] = w1;
        __syncthreads();
        #pragma unroll
        for (int k = 0; k < 16; k++) {
            float4 af0 = *(float4*)&As[k][ty*8];
            float4 af1 = *(float4*)&As[k][ty*8+4];
            float4 wf0 = *(float4*)&Ws[k][tx*8];
            float4 wf1 = *(float4*)&Ws[k][tx*8+4];
            float ar[8] = {af0.x, af0.y, af0.z, af0.w, af1.x, af1.y, af1.z, af1.w};
            float wr[8] = {wf0.x, wf0.y, wf0.z, wf0.w, wf1.x, wf1.y, wf1.z, wf1.w};
            #pragma unroll
            for (int i = 0; i < 8; i++)
                #pragma unroll
                for (int j = 0; j < 8; j++)
                    acc[i][j] += ar[i]*wr[j];
        }
        __syncthreads();
    }

    #pragma unroll
    for (int i = 0; i < 8; i++) {
        int row = bm + ty*8 + i;
        #pragma unroll
        for (int j = 0; j < 8; j++) {
            int col = bn + tx*8 + j;
            float v = acc[i][j] + bias[col];
            if (EPI == E_GELU) v = gelu_tanh(v);
            if (EPI == E_ADD)  v += R[(size_t)row*Nc + col];
            if (EPI == E_PYR) {
                long addr = (long)(row >> 9)*327680 + pyr_base + (long)col*512 + (row & 511);
                C[addr] = v;
            } else {
                C[(size_t)row*Nc + col] = v;
            }
        }
    }
}

// ---------------- LayerNorm + pos ----------------
__global__ __launch_bounds__(256) void ln_pos_k(
    const float* __restrict__ T, const float* __restrict__ g,
    const float* __restrict__ b, const float* __restrict__ pos,
    float* __restrict__ H)
{
    int warp = threadIdx.x >> 5, lane = threadIdx.x & 31;
    int row = blockIdx.x*8 + warp;
    const float* tr = T + (size_t)row*256;
    float v[8]; float s = 0.f, q = 0.f;
    #pragma unroll
    for (int i = 0; i < 8; i++) { v[i] = tr[i*32 + lane]; s += v[i]; q += v[i]*v[i]; }
    #pragma unroll
    for (int o = 16; o; o >>= 1) {
        s += __shfl_xor_sync(~0u, s, o);
        q += __shfl_xor_sync(~0u, q, o);
    }
    float mean = s*(1.f/256.f);
    float var  = q*(1.f/256.f) - mean*mean;
    float istd = rsqrtf(var + 1e-5f);
    int n = row & 511;
    float* hr = H + (size_t)row*256;
    const float* pr = pos + n*256;
    #pragma unroll
    for (int i = 0; i < 8; i++) {
        int c = i*32 + lane;
        hr[c] = (v[i]-mean)*istd*g[c] + b[c] + pr[c];
    }
}

// ---------------- BatchNorm (deterministic, 3 kernels) ----------------
__global__ __launch_bounds__(256) void bn_part_k(const float* __restrict__ X, float* __restrict__ part) {
    int c = threadIdx.x;
    int r0 = blockIdx.x * 64;
    float s = 0.f, q = 0.f;
    for (int r = 0; r < 64; r++) {
        float v = X[(size_t)(r0+r)*256 + c];
        s += v; q += v*v;
    }
    part[blockIdx.x*256 + c] = s;
    part[128*256 + blockIdx.x*256 + c] = q;
}

__global__ void bn_fin_k(const float* __restrict__ part, const float* __restrict__ g,
                         const float* __restrict__ b, float* __restrict__ sc) {
    int c = threadIdx.x;
    float s = 0.f, q = 0.f;
    for (int i = 0; i < 128; i++) { s += part[i*256 + c]; q += part[32768 + i*256 + c]; }
    float mean = s*(1.f/8192.f);
    float var  = q*(1.f/8192.f) - mean*mean;
    float istd = rsqrtf(var + 1e-5f);
    float scale = g[c]*istd;
    sc[c] = scale;
    sc[256 + c] = b[c] - mean*scale;
}

__global__ void bn_apply_k(float* __restrict__ X, const float* __restrict__ sc) {
    int i = blockIdx.x*256 + threadIdx.x;   // float4 index
    float4 v = ((float4*)X)[i];
    int c = (i*4) & 255;
    v.x = v.x*sc[c]   + sc[256+c];
    v.y = v.y*sc[c+1] + sc[257+c];
    v.z = v.z*sc[c+2] + sc[258+c];
    v.w = v.w*sc[c+3] + sc[259+c];
    ((float4*)X)[i] = v;
}

// ---------------- block-sparse windowed attention ----------------
// one block per (b, head, query-block); band = key blocks qb-2..qb+2 (160 keys)
__global__ __launch_bounds__(256) void attn_k(const float* __restrict__ QKV, float* __restrict__ AO) {
    __shared__ float qs[32][33];
    __shared__ float kv[160][33];
    __shared__ float S[32][160];
    int bid = blockIdx.x;
    int qb = bid & 15, h = (bid >> 4) & 7, b = bid >> 7;
    int t = threadIdx.x;
    const float* base = QKV + (size_t)b*512*768;

    { // load Q block
        int qr = t >> 3, e = (t & 7)*4;
        float4 v = *(const float4*)&base[(size_t)(qb*32 + qr)*768 + h*32 + e];
        qs[qr][e] = v.x; qs[qr][e+1] = v.y; qs[qr][e+2] = v.z; qs[qr][e+3] = v.w;
    }
    { // load K band
        int e = (t & 7)*4;
        for (int j = t >> 3; j < 160; j += 32) {
            int kb = qb + (j >> 5) - 2;
            float4 v = make_float4(0.f,0.f,0.f,0.f);
            if (kb >= 0 && kb < 16)
                v = *(const float4*)&base[(size_t)(kb*32 + (j & 31))*768 + 256 + h*32 + e];
            kv[j][e] = v.x; kv[j][e+1] = v.y; kv[j][e+2] = v.z; kv[j][e+3] = v.w;
        }
    }
    __syncthreads();

    const float scale = 0.17677669529663687f;  // 1/sqrt(32)
    #pragma unroll
    for (int ii = 0; ii < 20; ii++) {
        int idx = t + ii*256;
        int qr = idx/160, j = idx - qr*160;
        int kb = qb + (j >> 5) - 2;
        float a = 0.f;
        #pragma unroll
        for (int k = 0; k < 32; k++) a += qs[qr][k]*kv[j][k];
        S[qr][j] = (kb >= 0 && kb < 16) ? a*scale : -1e9f;
    }
    __syncthreads();

    { // softmax, one warp per 4 rows
        int warp = t >> 5, lane = t & 31;
        for (int qr = warp; qr < 32; qr += 8) {
            float vv[5]; float m = -1e30f;
            #pragma unroll
            for (int i = 0; i < 5; i++) { vv[i] = S[qr][lane + 32*i]; m = fmaxf(m, vv[i]); }
            #pragma unroll
            for (int o = 16; o; o >>= 1) m = fmaxf(m, __shfl_xor_sync(~0u, m, o));
            float s = 0.f;
            #pragma unroll
            for (int i = 0; i < 5; i++) { vv[i] = expf(vv[i] - m); s += vv[i]; }
            #pragma unroll
            for (int o = 16; o; o >>= 1) s += __shfl_xor_sync(~0u, s, o);
            float inv = 1.f/s;
            #pragma unroll
            for (int i = 0; i < 5; i++) S[qr][lane + 32*i] = vv[i]*inv;
        }
    }
    { // load V band into kv (K reads finished before scores sync)
        int e = (t & 7)*4;
        for (int j = t >> 3; j < 160; j += 32) {
            int kb = qb + (j >> 5) - 2;
            float4 v = make_float4(0.f,0.f,0.f,0.f);
            if (kb >= 0 && kb < 16)
                v = *(const float4*)&base[(size_t)(kb*32 + (j & 31))*768 + 512 + h*32 + e];
            kv[j][e] = v.x; kv[j][e+1] = v.y; kv[j][e+2] = v.z; kv[j][e+3] = v.w;
        }
    }
    __syncthreads();

    #pragma unroll
    for (int ii = 0; ii < 4; ii++) {
        int idx = t + ii*256;
        int qr = idx >> 5, e = idx & 31;
        float a = 0.f;
        #pragma unroll 8
        for (int j = 0; j < 160; j++) a += S[qr][j]*kv[j][e];
        AO[((size_t)b*512 + qb*32 + qr)*256 + h*32 + e] = a;
    }
}

// ---------------- fcl: [16 x 327680] @ [327680 x 128], deterministic -------
__global__ __launch_bounds__(128) void fcl_part_k(
    const float* __restrict__ P, const float* __restrict__ W, float* __restrict__ out)
{
    __shared__ float As[16][128];
    int gch = blockIdx.x;        // 160 chunks of 2048
    int j = threadIdx.x;
    float acc[16];
    #pragma unroll
    for (int b = 0; b < 16; b++) acc[b] = 0.f;
    int k0 = gch*2048;
    for (int s = 0; s < 16; s++) {
        int kb = k0 + s*128;
        __syncthreads();
        for (int idx = j; idx < 2048; idx += 128) {
            int b = idx >> 7, kk = idx & 127;
            As[b][kk] = P[(size_t)b*327680 + kb + kk];
        }
        __syncthreads();
        #pragma unroll 4
        for (int kk = 0; kk < 128; kk++) {
            float w = W[(size_t)(kb + kk)*128 + j];
            #pragma unroll
            for (int b = 0; b < 16; b++) acc[b] += As[b][kk]*w;
        }
    }
    #pragma unroll
    for (int b = 0; b < 16; b++) out[(size_t)gch*2048 + b*128 + j] = acc[b];
}

__global__ void fcl_red_k(const float* __restrict__ part, const float* __restrict__ bias,
                          float* __restrict__ add) {
    int idx = blockIdx.x*256 + threadIdx.x;   // 2048 outputs
    int j = idx & 127;
    float s = 0.f;
    for (int gc = 0; gc < 160; gc++) s += part[(size_t)gc*2048 + idx];
    add[idx] = s + bias[j];
}

// ---------------- addbn + heads (single block) ----------------
__global__ __launch_bounds__(256) void heads_k(
    const float* __restrict__ add, const float* __restrict__ abg, const float* __restrict__ abb,
    const float* __restrict__ cW1, const float* __restrict__ cb1,
    const float* __restrict__ cW2, const float* __restrict__ cb2,
    const float* __restrict__ bW1, const float* __restrict__ bb1,
    const float* __restrict__ bW2, const float* __restrict__ bb2,
    float* __restrict__ out)
{
    __shared__ float sA[16][128];
    __shared__ float sH[16][256];
    __shared__ float sL[16][45];
    int t = threadIdx.x;
    if (t < 128) {
        float s = 0.f, q = 0.f;
        for (int b = 0; b < 16; b++) { float v = add[b*128 + t]; s += v; q += v*v; }
        float mean = s*(1.f/16.f);
        float var  = q*(1.f/16.f) - mean*mean;
        float istd = rsqrtf(var + 1e-5f);
        float sc = abg[t]*istd, sh = abb[t] - mean*sc;
        for (int b = 0; b < 16; b++) sA[b][t] = add[b*128 + t]*sc + sh;
    }
    __syncthreads();
    // cls hidden (relu), 16x256
    for (int idx = t; idx < 4096; idx += 256) {
        int b = idx >> 8, u = idx & 255;
        float a = cb1[u];
        for (int c = 0; c < 128; c++) a += sA[b][c]*cW1[c*256 + u];
        sH[b][u] = fmaxf(a, 0.f);
    }
    __syncthreads();
    // cls logits 16x45
    for (int idx = t; idx < 720; idx += 256) {
        int b = idx/45, o = idx - b*45;
        float a = cb2[o];
        for (int u = 0; u < 256; u++) a += sH[b][u]*cW2[u*45 + o];
        sL[b][o] = a;
    }
    __syncthreads();
    // softmax over 45 + write cls
    if (t < 16) {
        int b = t;
        float m = -1e30f;
        for (int o = 0; o < 45; o++) m = fmaxf(m, sL[b][o]);
        float s = 0.f; float e[45];
        for (int o = 0; o < 45; o++) { e[o] = expf(sL[b][o] - m); s += e[o]; }
        float inv = 1.f/s;
        for (int o = 0; o < 45; o++)
            out[b*81 + (o/5)*9 + (o%5)] = e[o]*inv;
    }
    __syncthreads();
    // box hidden (relu) 16x128 (reuse sH)
    for (int idx = t; idx < 2048; idx += 256) {
        int b = idx >> 7, u = idx & 127;
        float a = bb1[u];
        for (int c = 0; c < 128; c++) a += sA[b][c]*bW1[c*128 + u];
        sH[b][u] = fmaxf(a, 0.f);
    }
    __syncthreads();
    // box out 16x36
    for (int idx = t; idx < 576; idx += 256) {
        int b = idx/36, o = idx - b*36;
        float a = bb2[o];
        for (int u = 0; u < 128; u++) a += sH[b][u]*bW2[u*36 + o];
        out[b*81 + (o/4)*9 + 5 + (o%4)] = a;
    }
}

// ---------------- host ----------------
extern "C" void kernel_launch(void* const* d_in, const int* in_sizes, int n_in,
                              void* d_out, int out_size) {
    const float* x       = (const float*)d_in[0];
    const float* patch_W = (const float*)d_in[1];
    const float* patch_b = (const float*)d_in[2];
    const float* ln_g    = (const float*)d_in[3];
    const float* ln_b    = (const float*)d_in[4];
    const float* ff_W1   = (const float*)d_in[5];
    const float* ff_b1   = (const float*)d_in[6];
    const float* ff_W2   = (const float*)d_in[7];
    const float* ff_b2   = (const float*)d_in[8];
    const float* Wqkv    = (const float*)d_in[9];
    const float* bqkv    = (const float*)d_in[10];
    const float* Wo      = (const float*)d_in[11];
    const float* bo      = (const float*)d_in[12];
    const float* bn1_g   = (const float*)d_in[13];
    const float* bn1_b   = (const float*)d_in[14];
    const float* bn2_g   = (const float*)d_in[15];
    const float* bn2_b   = (const float*)d_in[16];
    const float* pyr_W   = (const float*)d_in[17];
    const float* pyr_b   = (const float*)d_in[18];
    const float* fcl_W   = (const float*)d_in[19];
    const float* fcl_b   = (const float*)d_in[20];
    const float* addbn_g = (const float*)d_in[21];
    const float* addbn_b = (const float*)d_in[22];
    const float* cls_W1  = (const float*)d_in[23];
    const float* cls_b1  = (const float*)d_in[24];
    const float* cls_W2  = (const float*)d_in[25];
    const float* cls_b2  = (const float*)d_in[26];
    const float* box_W1  = (const float*)d_in[27];
    const float* box_b1  = (const float*)d_in[28];
    const float* box_W2  = (const float*)d_in[29];
    const float* box_b2  = (const float*)d_in[30];

    static float *X=nullptr,*T,*H,*G,*F,*QKV,*AO,*POS,*BNP,*BNS,*PF,*FP,*ADD;
    if (!X) {
        cudaGetSymbolAddress((void**)&X,  g_X);
        cudaGetSymbolAddress((void**)&T,  g_T);
        cudaGetSymbolAddress((void**)&H,  g_H);
        cudaGetSymbolAddress((void**)&G,  g_G);
        cudaGetSymbolAddress((void**)&F,  g_F);
        cudaGetSymbolAddress((void**)&QKV,g_QKV);
        cudaGetSymbolAddress((void**)&AO, g_AO);
        cudaGetSymbolAddress((void**)&POS,g_POS);
        cudaGetSymbolAddress((void**)&BNP,g_BNP);
        cudaGetSymbolAddress((void**)&BNS,g_BNS);
        cudaGetSymbolAddress((void**)&PF, g_PF);
        cudaGetSymbolAddress((void**)&FP, g_FP);
        cudaGetSymbolAddress((void**)&ADD,g_ADD);
    }

    pos_k<<<512,256>>>(POS);

    for (int it = 0; it < 5; it++) {
        const float* src = (it == 0) ? x : X;
        gemm_k<E_NONE><<<dim3(2,64),256>>>(src, patch_W, patch_b, nullptr, T, MTOK, 256, 256, 0);
        ln_pos_k<<<1024,256>>>(T, ln_g, ln_b, POS, H);
        gemm_k<E_GELU><<<dim3(8,64),256>>>(H, ff_W1, ff_b1, nullptr, G, MTOK, 1024, 256, 0);
        gemm_k<E_NONE><<<dim3(2,64),256>>>(G, ff_W2, ff_b2, nullptr, F, MTOK, 256, 1024, 0);
        gemm_k<E_NONE><<<dim3(6,64),256>>>(F, Wqkv, bqkv, nullptr, QKV, MTOK, 768, 256, 0);
        attn_k<<<2048,256>>>(QKV, AO);
        gemm_k<E_ADD><<<dim3(2,64),256>>>(AO, Wo, bo, H, T, MTOK, 256, 256, 0);
        bn_part_k<<<128,256>>>(T, BNP);
        bn_fin_k<<<1,256>>>(BNP, bn1_g, bn1_b, BNS);
        bn_apply_k<<<2048,256>>>(T, BNS);
        gemm_k<E_GELU><<<dim3(8,64),256>>>(T, ff_W1, ff_b1, nullptr, G, MTOK, 1024, 256, 0);
        gemm_k<E_ADD><<<dim3(2,64),256>>>(G, ff_W2, ff_b2, T, X, MTOK, 256, 1024, 0);
        bn_part_k<<<128,256>>>(X, BNP);
        bn_fin_k<<<1,256>>>(BNP, bn2_g, bn2_b, BNS);
        bn_apply_k<<<2048,256>>>(X, BNS);
        gemm_k<E_PYR><<<dim3(1,64),256>>>(X, pyr_W + (size_t)it*256*128, pyr_b + it*128,
                                          nullptr, PF, MTOK, 128, 256, it*65536);
    }

    fcl_part_k<<<160,128>>>(PF, fcl_W, FP);
    fcl_red_k<<<8,256>>>(FP, fcl_b, ADD);
    heads_k<<<1,256>>>(ADD, addbn_g, addbn_b,
                       cls_W1, cls_b1, cls_W2, cls_b2,
                       box_W1, box_b1, box_W2, box_b2,
                       (float*)d_out);
}

// round 3
// speedup vs baseline: 1.0997x; 1.0997x over previous
#include <cuda_runtime.h>
#include <math.h>
#include <stdint.h>

// ---------------- scratch (device globals; no allocation) ----------------
#define MTOK (8192)          // B*N
#define DMODEL 256
#define HID 1024

__device__ float g_X[MTOK*DMODEL];
__device__ float g_T[MTOK*DMODEL];
__device__ float g_H[MTOK*DMODEL];
__device__ float g_G[MTOK*HID];
__device__ float g_F[MTOK*DMODEL];
__device__ float g_QKV[MTOK*3*DMODEL];
__device__ float g_AO[MTOK*DMODEL];
__device__ float g_POS[512*DMODEL];
__device__ float g_BNP[2*128*DMODEL];
__device__ float g_BNS[2*DMODEL];
__device__ float g_PF[16*327680];
__device__ float g_FP[160*16*128];
__device__ float g_ADD[16*128];

// ---------------- helpers ----------------
__device__ __forceinline__ float gelu_tanh(float x) {
    float x3 = x*x*x;
    return 0.5f*x*(1.f + tanhf(0.7978845608028654f*(x + 0.044715f*x3)));
}

__device__ __forceinline__ void tf32_split(float f, float& hi, float& lo) {
    uint32_t h; asm("cvt.rna.tf32.f32 %0, %1;" : "=r"(h) : "f"(f));
    hi = __uint_as_float(h);
    float l = f - hi;
    uint32_t lu; asm("cvt.rna.tf32.f32 %0, %1;" : "=r"(lu) : "f"(l));
    lo = __uint_as_float(lu);
}

__device__ __forceinline__ void mma_tf32(float c[4],
    uint32_t a0, uint32_t a1, uint32_t a2, uint32_t a3,
    uint32_t b0, uint32_t b1)
{
    asm volatile(
        "mma.sync.aligned.m16n8k8.row.col.f32.tf32.tf32.f32 "
        "{%0,%1,%2,%3}, {%4,%5,%6,%7}, {%8,%9}, {%0,%1,%2,%3};\n"
        : "+f"(c[0]), "+f"(c[1]), "+f"(c[2]), "+f"(c[3])
        : "r"(a0), "r"(a1), "r"(a2), "r"(a3), "r"(b0), "r"(b1));
}

// ---------------- positional table ----------------
__global__ void pos_k(float* __restrict__ pos) {
    int idx = blockIdx.x*256 + threadIdx.x;
    if (idx >= 512*256) return;
    int n = idx >> 8, d = idx & 255;
    double ang = (double)n / pow(10000.0, (double)(2*(d>>1)) / 256.0);
    pos[idx] = (float)((d & 1) ? cos(ang) : sin(ang));
}

// ---------------- tensor-core GEMM (tf32x3): C = A@W + bias (+epilogue) ----
// block tile 128x128, k-tile 16, 8 warps (4 along M x 2 along N), warp 32x64
#define E_NONE 0
#define E_GELU 1
#define E_ADD  2
#define E_PYR  3

template<int EPI>
__global__ __launch_bounds__(256) void gemm_tc(
    const float* __restrict__ A, const float* __restrict__ W,
    const float* __restrict__ bias, const float* __restrict__ R,
    float* __restrict__ C, int M, int Nc, int K, int pyr_base)
{
    __shared__ float Ah[128][20];
    __shared__ float Al[128][20];
    __shared__ float Bh[16][132];
    __shared__ float Bl[16][132];

    int t = threadIdx.x;
    int lane = t & 31, warp = t >> 5;
    int g = lane >> 2, tid4 = lane & 3;
    int warpM = (warp & 3) * 32;
    int warpN = (warp >> 2) * 64;
    int bm = blockIdx.y * 128, bn = blockIdx.x * 128;

    float acc[2][8][4];
    #pragma unroll
    for (int i = 0; i < 2; i++)
        #pragma unroll
        for (int j = 0; j < 8; j++)
            #pragma unroll
            for (int r = 0; r < 4; r++) acc[i][j][r] = 0.f;

    int aRow = t >> 1, aK0 = (t & 1) * 8;
    int bK = t >> 4, bN0 = (t & 15) * 8;

    for (int kt = 0; kt < K; kt += 16) {
        // stage A tile 128x16 (split hi/lo)
        #pragma unroll
        for (int q = 0; q < 2; q++) {
            float4 v = *(const float4*)&A[(size_t)(bm + aRow)*K + kt + aK0 + q*4];
            float f[4] = {v.x, v.y, v.z, v.w};
            #pragma unroll
            for (int e = 0; e < 4; e++) {
                float hi, lo; tf32_split(f[e], hi, lo);
                Ah[aRow][aK0 + q*4 + e] = hi;
                Al[aRow][aK0 + q*4 + e] = lo;
            }
        }
        // stage B tile 16x128 (split hi/lo)
        #pragma unroll
        for (int q = 0; q < 2; q++) {
            float4 v = *(const float4*)&W[(size_t)(kt + bK)*Nc + bn + bN0 + q*4];
            float f[4] = {v.x, v.y, v.z, v.w};
            #pragma unroll
            for (int e = 0; e < 4; e++) {
                float hi, lo; tf32_split(f[e], hi, lo);
                Bh[bK][bN0 + q*4 + e] = hi;
                Bl[bK][bN0 + q*4 + e] = lo;
            }
        }
        __syncthreads();

        #pragma unroll
        for (int k8 = 0; k8 < 16; k8 += 8) {
            uint32_t ah[2][4], al[2][4];
            #pragma unroll
            for (int mt = 0; mt < 2; mt++) {
                int r0 = warpM + mt*16 + g;
                ah[mt][0] = __float_as_uint(Ah[r0  ][k8 + tid4]);
                ah[mt][1] = __float_as_uint(Ah[r0+8][k8 + tid4]);
                ah[mt][2] = __float_as_uint(Ah[r0  ][k8 + tid4 + 4]);
                ah[mt][3] = __float_as_uint(Ah[r0+8][k8 + tid4 + 4]);
                al[mt][0] = __float_as_uint(Al[r0  ][k8 + tid4]);
                al[mt][1] = __float_as_uint(Al[r0+8][k8 + tid4]);
                al[mt][2] = __float_as_uint(Al[r0  ][k8 + tid4 + 4]);
                al[mt][3] = __float_as_uint(Al[r0+8][k8 + tid4 + 4]);
            }
            #pragma unroll
            for (int nt = 0; nt < 8; nt++) {
                int c0 = warpN + nt*8 + g;
                uint32_t bh0 = __float_as_uint(Bh[k8 + tid4    ][c0]);
                uint32_t bh1 = __float_as_uint(Bh[k8 + tid4 + 4][c0]);
                uint32_t bl0 = __float_as_uint(Bl[k8 + tid4    ][c0]);
                uint32_t bl1 = __float_as_uint(Bl[k8 + tid4 + 4][c0]);
                #pragma unroll
                for (int mt = 0; mt < 2; mt++) {
                    mma_tf32(acc[mt][nt], al[mt][0], al[mt][1], al[mt][2], al[mt][3], bh0, bh1);
                    mma_tf32(acc[mt][nt], ah[mt][0], ah[mt][1], ah[mt][2], ah[mt][3], bl0, bl1);
                    mma_tf32(acc[mt][nt], ah[mt][0], ah[mt][1], ah[mt][2], ah[mt][3], bh0, bh1);
                }
            }
        }
        __syncthreads();
    }

    // epilogue
    #pragma unroll
    for (int nt = 0; nt < 8; nt++) {
        int col = bn + warpN + nt*8 + tid4*2;
        float bv0 = bias[col], bv1 = bias[col+1];
        #pragma unroll
        for (int mt = 0; mt < 2; mt++) {
            #pragma unroll
            for (int h = 0; h < 2; h++) {
                int row = bm + warpM + mt*16 + g + h*8;
                float v0 = acc[mt][nt][h*2+0] + bv0;
                float v1 = acc[mt][nt][h*2+1] + bv1;
                if (EPI == E_GELU) { v0 = gelu_tanh(v0); v1 = gelu_tanh(v1); }
                if (EPI == E_ADD) {
                    float2 r = *(const float2*)&R[(size_t)row*Nc + col];
                    v0 += r.x; v1 += r.y;
                }
                if (EPI == E_PYR) {
                    long b0 = (long)(row >> 9)*327680 + pyr_base + (row & 511);
                    C[b0 + (long)col*512]     = v0;
                    C[b0 + (long)(col+1)*512] = v1;
                } else {
                    float2 o; o.x = v0; o.y = v1;
                    *(float2*)&C[(size_t)row*Nc + col] = o;
                }
            }
        }
    }
}

// ---------------- LayerNorm + pos ----------------
__global__ __launch_bounds__(256) void ln_pos_k(
    const float* __restrict__ T, const float* __restrict__ g,
    const float* __restrict__ b, const float* __restrict__ pos,
    float* __restrict__ H)
{
    int warp = threadIdx.x >> 5, lane = threadIdx.x & 31;
    int row = blockIdx.x*8 + warp;
    const float* tr = T + (size_t)row*256;
    float v[8]; float s = 0.f, q = 0.f;
    #pragma unroll
    for (int i = 0; i < 8; i++) { v[i] = tr[i*32 + lane]; s += v[i]; q += v[i]*v[i]; }
    #pragma unroll
    for (int o = 16; o; o >>= 1) {
        s += __shfl_xor_sync(~0u, s, o);
        q += __shfl_xor_sync(~0u, q, o);
    }
    float mean = s*(1.f/256.f);
    float var  = q*(1.f/256.f) - mean*mean;
    float istd = rsqrtf(var + 1e-5f);
    int n = row & 511;
    float* hr = H + (size_t)row*256;
    const float* pr = pos + n*256;
    #pragma unroll
    for (int i = 0; i < 8; i++) {
        int c = i*32 + lane;
        hr[c] = (v[i]-mean)*istd*g[c] + b[c] + pr[c];
    }
}

// ---------------- BatchNorm (deterministic, 3 kernels) ----------------
__global__ __launch_bounds__(256) void bn_part_k(const float* __restrict__ X, float* __restrict__ part) {
    int c = threadIdx.x;
    int r0 = blockIdx.x * 64;
    float s = 0.f, q = 0.f;
    for (int r = 0; r < 64; r++) {
        float v = X[(size_t)(r0+r)*256 + c];
        s += v; q += v*v;
    }
    part[blockIdx.x*256 + c] = s;
    part[128*256 + blockIdx.x*256 + c] = q;
}

__global__ void bn_fin_k(const float* __restrict__ part, const float* __restrict__ g,
                         const float* __restrict__ b, float* __restrict__ sc) {
    int c = threadIdx.x;
    float s = 0.f, q = 0.f;
    for (int i = 0; i < 128; i++) { s += part[i*256 + c]; q += part[32768 + i*256 + c]; }
    float mean = s*(1.f/8192.f);
    float var  = q*(1.f/8192.f) - mean*mean;
    float istd = rsqrtf(var + 1e-5f);
    float scale = g[c]*istd;
    sc[c] = scale;
    sc[256 + c] = b[c] - mean*scale;
}

__global__ void bn_apply_k(float* __restrict__ X, const float* __restrict__ sc) {
    int i = blockIdx.x*256 + threadIdx.x;
    float4 v = ((float4*)X)[i];
    int c = (i*4) & 255;
    v.x = v.x*sc[c]   + sc[256+c];
    v.y = v.y*sc[c+1] + sc[257+c];
    v.z = v.z*sc[c+2] + sc[258+c];
    v.w = v.w*sc[c+3] + sc[259+c];
    ((float4*)X)[i] = v;
}

// ---------------- block-sparse windowed attention ----------------
__global__ __launch_bounds__(256) void attn_k(const float* __restrict__ QKV, float* __restrict__ AO) {
    __shared__ float qs[32][33];
    __shared__ float kv[160][33];
    __shared__ float S[32][160];
    int bid = blockIdx.x;
    int qb = bid & 15, h = (bid >> 4) & 7, b = bid >> 7;
    int t = threadIdx.x;
    const float* base = QKV + (size_t)b*512*768;

    {
        int qr = t >> 3, e = (t & 7)*4;
        float4 v = *(const float4*)&base[(size_t)(qb*32 + qr)*768 + h*32 + e];
        qs[qr][e] = v.x; qs[qr][e+1] = v.y; qs[qr][e+2] = v.z; qs[qr][e+3] = v.w;
    }
    {
        int e = (t & 7)*4;
        for (int j = t >> 3; j < 160; j += 32) {
            int kb = qb + (j >> 5) - 2;
            float4 v = make_float4(0.f,0.f,0.f,0.f);
            if (kb >= 0 && kb < 16)
                v = *(const float4*)&base[(size_t)(kb*32 + (j & 31))*768 + 256 + h*32 + e];
            kv[j][e] = v.x; kv[j][e+1] = v.y; kv[j][e+2] = v.z; kv[j][e+3] = v.w;
        }
    }
    __syncthreads();

    const float scale = 0.17677669529663687f;
    #pragma unroll
    for (int ii = 0; ii < 20; ii++) {
        int idx = t + ii*256;
        int qr = idx/160, j = idx - qr*160;
        int kb = qb + (j >> 5) - 2;
        float a = 0.f;
        #pragma unroll
        for (int k = 0; k < 32; k++) a += qs[qr][k]*kv[j][k];
        S[qr][j] = (kb >= 0 && kb < 16) ? a*scale : -1e9f;
    }
    __syncthreads();

    {
        int warp = t >> 5, lane = t & 31;
        for (int qr = warp; qr < 32; qr += 8) {
            float vv[5]; float m = -1e30f;
            #pragma unroll
            for (int i = 0; i < 5; i++) { vv[i] = S[qr][lane + 32*i]; m = fmaxf(m, vv[i]); }
            #pragma unroll
            for (int o = 16; o; o >>= 1) m = fmaxf(m, __shfl_xor_sync(~0u, m, o));
            float s = 0.f;
            #pragma unroll
            for (int i = 0; i < 5; i++) { vv[i] = expf(vv[i] - m); s += vv[i]; }
            #pragma unroll
            for (int o = 16; o; o >>= 1) s += __shfl_xor_sync(~0u, s, o);
            float inv = 1.f/s;
            #pragma unroll
            for (int i = 0; i < 5; i++) S[qr][lane + 32*i] = vv[i]*inv;
        }
    }
    {
        int e = (t & 7)*4;
        for (int j = t >> 3; j < 160; j += 32) {
            int kb = qb + (j >> 5) - 2;
            float4 v = make_float4(0.f,0.f,0.f,0.f);
            if (kb >= 0 && kb < 16)
                v = *(const float4*)&base[(size_t)(kb*32 + (j & 31))*768 + 512 + h*32 + e];
            kv[j][e] = v.x; kv[j][e+1] = v.y; kv[j][e+2] = v.z; kv[j][e+3] = v.w;
        }
    }
    __syncthreads();

    #pragma unroll
    for (int ii = 0; ii < 4; ii++) {
        int idx = t + ii*256;
        int qr = idx >> 5, e = idx & 31;
        float a = 0.f;
        #pragma unroll 8
        for (int j = 0; j < 160; j++) a += S[qr][j]*kv[j][e];
        AO[((size_t)b*512 + qb*32 + qr)*256 + h*32 + e] = a;
    }
}

// ---------------- fcl: [16 x 327680] @ [327680 x 128], deterministic -------
__global__ __launch_bounds__(128) void fcl_part_k(
    const float* __restrict__ P, const float* __restrict__ W, float* __restrict__ out)
{
    __shared__ float As[16][128];
    int gch = blockIdx.x;
    int j = threadIdx.x;
    float acc[16];
    #pragma unroll
    for (int b = 0; b < 16; b++) acc[b] = 0.f;
    int k0 = gch*2048;
    for (int s = 0; s < 16; s++) {
        int kb = k0 + s*128;
        __syncthreads();
        for (int idx = j; idx < 2048; idx += 128) {
            int b = idx >> 7, kk = idx & 127;
            As[b][kk] = P[(size_t)b*327680 + kb + kk];
        }
        __syncthreads();
        #pragma unroll 4
        for (int kk = 0; kk < 128; kk++) {
            float w = W[(size_t)(kb + kk)*128 + j];
            #pragma unroll
            for (int b = 0; b < 16; b++) acc[b] += As[b][kk]*w;
        }
    }
    #pragma unroll
    for (int b = 0; b < 16; b++) out[(size_t)gch*2048 + b*128 + j] = acc[b];
}

__global__ void fcl_red_k(const float* __restrict__ part, const float* __restrict__ bias,
                          float* __restrict__ add) {
    int idx = blockIdx.x*256 + threadIdx.x;
    int j = idx & 127;
    float s = 0.f;
    for (int gc = 0; gc < 160; gc++) s += part[(size_t)gc*2048 + idx];
    add[idx] = s + bias[j];
}

// ---------------- addbn + heads (single block) ----------------
__global__ __launch_bounds__(256) void heads_k(
    const float* __restrict__ add, const float* __restrict__ abg, const float* __restrict__ abb,
    const float* __restrict__ cW1, const float* __restrict__ cb1,
    const float* __restrict__ cW2, const float* __restrict__ cb2,
    const float* __restrict__ bW1, const float* __restrict__ bb1,
    const float* __restrict__ bW2, const float* __restrict__ bb2,
    float* __restrict__ out)
{
    __shared__ float sA[16][128];
    __shared__ float sH[16][256];
    __shared__ float sL[16][45];
    int t = threadIdx.x;
    if (t < 128) {
        float s = 0.f, q = 0.f;
        for (int b = 0; b < 16; b++) { float v = add[b*128 + t]; s += v; q += v*v; }
        float mean = s*(1.f/16.f);
        float var  = q*(1.f/16.f) - mean*mean;
        float istd = rsqrtf(var + 1e-5f);
        float sc = abg[t]*istd, sh = abb[t] - mean*sc;
        for (int b = 0; b < 16; b++) sA[b][t] = add[b*128 + t]*sc + sh;
    }
    __syncthreads();
    for (int idx = t; idx < 4096; idx += 256) {
        int b = idx >> 8, u = idx & 255;
        float a = cb1[u];
        for (int c = 0; c < 128; c++) a += sA[b][c]*cW1[c*256 + u];
        sH[b][u] = fmaxf(a, 0.f);
    }
    __syncthreads();
    for (int idx = t; idx < 720; idx += 256) {
        int b = idx/45, o = idx - b*45;
        float a = cb2[o];
        for (int u = 0; u < 256; u++) a += sH[b][u]*cW2[u*45 + o];
        sL[b][o] = a;
    }
    __syncthreads();
    if (t < 16) {
        int b = t;
        float m = -1e30f;
        for (int o = 0; o < 45; o++) m = fmaxf(m, sL[b][o]);
        float s = 0.f; float e[45];
        for (int o = 0; o < 45; o++) { e[o] = expf(sL[b][o] - m); s += e[o]; }
        float inv = 1.f/s;
        for (int o = 0; o < 45; o++)
            out[b*81 + (o/5)*9 + (o%5)] = e[o]*inv;
    }
    __syncthreads();
    for (int idx = t; idx < 2048; idx += 256) {
        int b = idx >> 7, u = idx & 127;
        float a = bb1[u];
        for (int c = 0; c < 128; c++) a += sA[b][c]*bW1[c*128 + u];
        sH[b][u] = fmaxf(a, 0.f);
    }
    __syncthreads();
    for (int idx = t; idx < 576; idx += 256) {
        int b = idx/36, o = idx - b*36;
        float a = bb2[o];
        for (int u = 0; u < 128; u++) a += sH[b][u]*bW2[u*36 + o];
        out[b*81 + (o/4)*9 + 5 + (o%4)] = a;
    }
}

// ---------------- host ----------------
extern "C" void kernel_launch(void* const* d_in, const int* in_sizes, int n_in,
                              void* d_out, int out_size) {
    const float* x       = (const float*)d_in[0];
    const float* patch_W = (const float*)d_in[1];
    const float* patch_b = (const float*)d_in[2];
    const float* ln_g    = (const float*)d_in[3];
    const float* ln_b    = (const float*)d_in[4];
    const float* ff_W1   = (const float*)d_in[5];
    const float* ff_b1   = (const float*)d_in[6];
    const float* ff_W2   = (const float*)d_in[7];
    const float* ff_b2   = (const float*)d_in[8];
    const float* Wqkv    = (const float*)d_in[9];
    const float* bqkv    = (const float*)d_in[10];
    const float* Wo      = (const float*)d_in[11];
    const float* bo      = (const float*)d_in[12];
    const float* bn1_g   = (const float*)d_in[13];
    const float* bn1_b   = (const float*)d_in[14];
    const float* bn2_g   = (const float*)d_in[15];
    const float* bn2_b   = (const float*)d_in[16];
    const float* pyr_W   = (const float*)d_in[17];
    const float* pyr_b   = (const float*)d_in[18];
    const float* fcl_W   = (const float*)d_in[19];
    const float* fcl_b   = (const float*)d_in[20];
    const float* addbn_g = (const float*)d_in[21];
    const float* addbn_b = (const float*)d_in[22];
    const float* cls_W1  = (const float*)d_in[23];
    const float* cls_b1  = (const float*)d_in[24];
    const float* cls_W2  = (const float*)d_in[25];
    const float* cls_b2  = (const float*)d_in[26];
    const float* box_W1  = (const float*)d_in[27];
    const float* box_b1  = (const float*)d_in[28];
    const float* box_W2  = (const float*)d_in[29];
    const float* box_b2  = (const float*)d_in[30];

    static float *X=nullptr,*T,*H,*G,*F,*QKV,*AO,*POS,*BNP,*BNS,*PF,*FP,*ADD;
    if (!X) {
        cudaGetSymbolAddress((void**)&X,  g_X);
        cudaGetSymbolAddress((void**)&T,  g_T);
        cudaGetSymbolAddress((void**)&H,  g_H);
        cudaGetSymbolAddress((void**)&G,  g_G);
        cudaGetSymbolAddress((void**)&F,  g_F);
        cudaGetSymbolAddress((void**)&QKV,g_QKV);
        cudaGetSymbolAddress((void**)&AO, g_AO);
        cudaGetSymbolAddress((void**)&POS,g_POS);
        cudaGetSymbolAddress((void**)&BNP,g_BNP);
        cudaGetSymbolAddress((void**)&BNS,g_BNS);
        cudaGetSymbolAddress((void**)&PF, g_PF);
        cudaGetSymbolAddress((void**)&FP, g_FP);
        cudaGetSymbolAddress((void**)&ADD,g_ADD);
    }

    pos_k<<<512,256>>>(POS);

    for (int it = 0; it < 5; it++) {
        const float* src = (it == 0) ? x : X;
        gemm_tc<E_NONE><<<dim3(2,64),256>>>(src, patch_W, patch_b, nullptr, T, MTOK, 256, 256, 0);
        ln_pos_k<<<1024,256>>>(T, ln_g, ln_b, POS, H);
        gemm_tc<E_GELU><<<dim3(8,64),256>>>(H, ff_W1, ff_b1, nullptr, G, MTOK, 1024, 256, 0);
        gemm_tc<E_NONE><<<dim3(2,64),256>>>(G, ff_W2, ff_b2, nullptr, F, MTOK, 256, 1024, 0);
        gemm_tc<E_NONE><<<dim3(6,64),256>>>(F, Wqkv, bqkv, nullptr, QKV, MTOK, 768, 256, 0);
        attn_k<<<2048,256>>>(QKV, AO);
        gemm_tc<E_ADD><<<dim3(2,64),256>>>(AO, Wo, bo, H, T, MTOK, 256, 256, 0);
        bn_part_k<<<128,256>>>(T, BNP);
        bn_fin_k<<<1,256>>>(BNP, bn1_g, bn1_b, BNS);
        bn_apply_k<<<2048,256>>>(T, BNS);
        gemm_tc<E_GELU><<<dim3(8,64),256>>>(T, ff_W1, ff_b1, nullptr, G, MTOK, 1024, 256, 0);
        gemm_tc<E_ADD><<<dim3(2,64),256>>>(G, ff_W2, ff_b2, T, X, MTOK, 256, 1024, 0);
        bn_part_k<<<128,256>>>(X, BNP);
        bn_fin_k<<<1,256>>>(BNP, bn2_g, bn2_b, BNS);
        bn_apply_k<<<2048,256>>>(X, BNS);
        gemm_tc<E_PYR><<<dim3(1,64),256>>>(X, pyr_W + (size_t)it*256*128, pyr_b + it*128,
                                           nullptr, PF, MTOK, 128, 256, it*65536);
    }

    fcl_part_k<<<160,128>>>(PF, fcl_W, FP);
    fcl_red_k<<<8,256>>>(FP, fcl_b, ADD);
    heads_k<<<1,256>>>(ADD, addbn_g, addbn_b,
                       cls_W1, cls_b1, cls_W2, cls_b2,
                       box_W1, box_b1, box_W2, box_b2,
                       (float*)d_out);
}

// round 4
// speedup vs baseline: 1.5395x; 1.3998x over previous
#include <cuda_runtime.h>
#include <cuda_bf16.h>
#include <math.h>
#include <stdint.h>

// ---------------- sizes ----------------
#define MTOK 8192
#define DMODEL 256
#define HID 1024

// ---------------- fp32 scratch ----------------
__device__ float g_X[MTOK*DMODEL];      // residual stream (fp32, for BN stats / residual)
__device__ float g_T[MTOK*DMODEL];
__device__ float g_H[MTOK*DMODEL];      // LN+pos out fp32 (residual for Wo)
__device__ float g_QKV[MTOK*3*DMODEL];
__device__ float g_POS[512*DMODEL];
__device__ float g_BNP[2*128*DMODEL];
__device__ float g_BNS[2*DMODEL];
__device__ float g_PF[16*327680];
__device__ float g_FP[160*16*128];
__device__ float g_ADD[16*128];

// ---------------- bf16 hi/lo packed-pair scratch ([m][k/2] uint32) --------
__device__ uint32_t g_Xh[MTOK*128], g_Xl[MTOK*128];
__device__ uint32_t g_Hh[MTOK*128], g_Hl[MTOK*128];
__device__ uint32_t g_Th[MTOK*128], g_Tl[MTOK*128];
__device__ uint32_t g_Gh[MTOK*512], g_Gl[MTOK*512];
__device__ uint32_t g_Fh[MTOK*128], g_Fl[MTOK*128];
__device__ uint32_t g_AOh[MTOK*128], g_AOl[MTOK*128];
// weights, [n][k/2] layout
__device__ uint32_t g_Wph[256*128],  g_Wpl[256*128];   // patch   K=256 N=256
__device__ uint32_t g_W1h[1024*128], g_W1l[1024*128];  // ff1     K=256 N=1024
__device__ uint32_t g_W2h[256*512],  g_W2l[256*512];   // ff2     K=1024 N=256
__device__ uint32_t g_Wqh[768*128],  g_Wql[768*128];   // qkv     K=256 N=768
__device__ uint32_t g_Woh[256*128],  g_Wol[256*128];   // wo      K=256 N=256
__device__ uint32_t g_Pyh[5*128*128], g_Pyl[5*128*128];// pyr x5  K=256 N=128

// ---------------- helpers ----------------
__device__ __forceinline__ float gelu_tanh(float x) {
    float x3 = x*x*x;
    return 0.5f*x*(1.f + tanhf(0.7978845608028654f*(x + 0.044715f*x3)));
}

__device__ __forceinline__ void split_pack(float v0, float v1, uint32_t& ph, uint32_t& pl) {
    __nv_bfloat16 h0 = __float2bfloat16(v0), h1 = __float2bfloat16(v1);
    float r0 = v0 - __bfloat162float(h0), r1 = v1 - __bfloat162float(h1);
    __nv_bfloat16 l0 = __float2bfloat16(r0), l1 = __float2bfloat16(r1);
    ph = ((uint32_t)__bfloat16_as_ushort(h1) << 16) | (uint32_t)__bfloat16_as_ushort(h0);
    pl = ((uint32_t)__bfloat16_as_ushort(l1) << 16) | (uint32_t)__bfloat16_as_ushort(l0);
}

__device__ __forceinline__ void mma_bf16(float c[4],
    uint32_t a0, uint32_t a1, uint32_t a2, uint32_t a3, uint32_t b0, uint32_t b1)
{
    asm volatile(
        "mma.sync.aligned.m16n8k16.row.col.f32.bf16.bf16.f32 "
        "{%0,%1,%2,%3}, {%4,%5,%6,%7}, {%8,%9}, {%0,%1,%2,%3};\n"
        : "+f"(c[0]), "+f"(c[1]), "+f"(c[2]), "+f"(c[3])
        : "r"(a0), "r"(a1), "r"(a2), "r"(a3), "r"(b0), "r"(b1));
}

// ---------------- conversion kernels ----------------
// weight: W[K][N] fp32 -> hi/lo packed pairs in [n][k/2]
__global__ void wcvt_k(const float* __restrict__ W, uint32_t* __restrict__ Wh,
                       uint32_t* __restrict__ Wl, int K, int N) {
    int idx = blockIdx.x*256 + threadIdx.x;
    int KP = K >> 1;
    if (idx >= N*KP) return;
    int n = idx / KP, kp = idx - n*KP;
    float v0 = W[(size_t)(2*kp)*N + n];
    float v1 = W[(size_t)(2*kp+1)*N + n];
    split_pack(v0, v1, Wh[idx], Wl[idx]);
}

// activation row-major fp32 -> packed pairs [m][k/2]
__global__ void xcvt_k(const float* __restrict__ X, uint32_t* __restrict__ Xh,
                       uint32_t* __restrict__ Xl) {
    int idx = blockIdx.x*256 + threadIdx.x;   // pair index, MTOK*128 total
    float2 v = *(const float2*)&X[(size_t)idx*2];
    split_pack(v.x, v.y, Xh[idx], Xl[idx]);
}

// ---------------- positional table ----------------
__global__ void pos_k(float* __restrict__ pos) {
    int idx = blockIdx.x*256 + threadIdx.x;
    if (idx >= 512*256) return;
    int n = idx >> 8, d = idx & 255;
    double ang = (double)n / pow(10000.0, (double)(2*(d>>1)) / 256.0);
    pos[idx] = (float)((d & 1) ? cos(ang) : sin(ang));
}

// ---------------- bf16x3 tensor-core GEMM ----------------
// block 128x128, k-tile 32 (16 pairs), 8 warps (4M x 2N), warp tile 32x64
#define E_NONE 0   // fp32 out
#define E_GELU 1   // gelu -> packed pairs out
#define E_ADD  2   // + residual R -> fp32 out
#define E_PYR  3   // fp32 scatter for pyramid
#define E_CVT  4   // packed pairs out

template<int EPI>
__global__ __launch_bounds__(256) void gemm_bf(
    const uint32_t* __restrict__ Ahg, const uint32_t* __restrict__ Alg,
    const uint32_t* __restrict__ Bhg, const uint32_t* __restrict__ Blg,
    const float* __restrict__ bias, const float* __restrict__ R,
    float* __restrict__ C, uint32_t* __restrict__ Ch, uint32_t* __restrict__ Cl,
    int M, int Nc, int K, int pyr_base)
{
    __shared__ uint32_t sAh[128][20], sAl[128][20];
    __shared__ uint32_t sBh[128][20], sBl[128][20];

    int t = threadIdx.x;
    int lane = t & 31, warp = t >> 5;
    int g = lane >> 2, tid4 = lane & 3;
    int warpM = (warp & 3) * 32;
    int warpN = (warp >> 2) * 64;
    int bm = blockIdx.y * 128, bn = blockIdx.x * 128;
    int KP = K >> 1;

    float acc[2][8][4];
    #pragma unroll
    for (int i = 0; i < 2; i++)
        #pragma unroll
        for (int j = 0; j < 8; j++)
            #pragma unroll
            for (int r = 0; r < 4; r++) acc[i][j][r] = 0.f;

    int sr = t >> 1, sh = (t & 1) * 8;

    for (int kt = 0; kt < K; kt += 32) {
        int kp0 = kt >> 1;
        const uint32_t* pa = Ahg + (size_t)(bm + sr)*KP + kp0 + sh;
        const uint32_t* pal= Alg + (size_t)(bm + sr)*KP + kp0 + sh;
        const uint32_t* pb = Bhg + (size_t)(bn + sr)*KP + kp0 + sh;
        const uint32_t* pbl= Blg + (size_t)(bn + sr)*KP + kp0 + sh;
        *(uint4*)&sAh[sr][sh]   = *(const uint4*)pa;
        *(uint4*)&sAh[sr][sh+4] = *(const uint4*)(pa+4);
        *(uint4*)&sAl[sr][sh]   = *(const uint4*)pal;
        *(uint4*)&sAl[sr][sh+4] = *(const uint4*)(pal+4);
        *(uint4*)&sBh[sr][sh]   = *(const uint4*)pb;
        *(uint4*)&sBh[sr][sh+4] = *(const uint4*)(pb+4);
        *(uint4*)&sBl[sr][sh]   = *(const uint4*)pbl;
        *(uint4*)&sBl[sr][sh+4] = *(const uint4*)(pbl+4);
        __syncthreads();

        #pragma unroll
        for (int s = 0; s < 2; s++) {
            int ko = s*8;
            uint32_t ah[2][4], al[2][4];
            #pragma unroll
            for (int mt = 0; mt < 2; mt++) {
                int r0 = warpM + mt*16 + g;
                ah[mt][0] = sAh[r0  ][ko + tid4];
                ah[mt][1] = sAh[r0+8][ko + tid4];
                ah[mt][2] = sAh[r0  ][ko + tid4 + 4];
                ah[mt][3] = sAh[r0+8][ko + tid4 + 4];
                al[mt][0] = sAl[r0  ][ko + tid4];
                al[mt][1] = sAl[r0+8][ko + tid4];
                al[mt][2] = sAl[r0  ][ko + tid4 + 4];
                al[mt][3] = sAl[r0+8][ko + tid4 + 4];
            }
            #pragma unroll
            for (int nt = 0; nt < 8; nt++) {
                int c0 = warpN + nt*8 + g;
                uint32_t bh0 = sBh[c0][ko + tid4];
                uint32_t bh1 = sBh[c0][ko + tid4 + 4];
                uint32_t bl0 = sBl[c0][ko + tid4];
                uint32_t bl1 = sBl[c0][ko + tid4 + 4];
                #pragma unroll
                for (int mt = 0; mt < 2; mt++) {
                    mma_bf16(acc[mt][nt], ah[mt][0], ah[mt][1], ah[mt][2], ah[mt][3], bh0, bh1);
                    mma_bf16(acc[mt][nt], ah[mt][0], ah[mt][1], ah[mt][2], ah[mt][3], bl0, bl1);
                    mma_bf16(acc[mt][nt], al[mt][0], al[mt][1], al[mt][2], al[mt][3], bh0, bh1);
                }
            }
        }
        __syncthreads();
    }

    int NP = Nc >> 1;
    #pragma unroll
    for (int nt = 0; nt < 8; nt++) {
        int col = bn + warpN + nt*8 + tid4*2;
        float bv0 = bias[col], bv1 = bias[col+1];
        #pragma unroll
        for (int mt = 0; mt < 2; mt++) {
            #pragma unroll
            for (int h = 0; h < 2; h++) {
                int row = bm + warpM + mt*16 + g + h*8;
                float v0 = acc[mt][nt][h*2+0] + bv0;
                float v1 = acc[mt][nt][h*2+1] + bv1;
                if (EPI == E_GELU) { v0 = gelu_tanh(v0); v1 = gelu_tanh(v1); }
                if (EPI == E_ADD) {
                    float2 r = *(const float2*)&R[(size_t)row*Nc + col];
                    v0 += r.x; v1 += r.y;
                }
                if (EPI == E_GELU || EPI == E_CVT) {
                    uint32_t ph, pl;
                    split_pack(v0, v1, ph, pl);
                    size_t pi = (size_t)row*NP + (col >> 1);
                    Ch[pi] = ph; Cl[pi] = pl;
                } else if (EPI == E_PYR) {
                    long b0 = (long)(row >> 9)*327680 + pyr_base + (row & 511);
                    C[b0 + (long)col*512]     = v0;
                    C[b0 + (long)(col+1)*512] = v1;
                } else {
                    float2 o; o.x = v0; o.y = v1;
                    *(float2*)&C[(size_t)row*Nc + col] = o;
                }
            }
        }
    }
}

// ---------------- LayerNorm + pos (fp32 out + packed pairs out) -----------
__global__ __launch_bounds__(256) void ln_pos_k(
    const float* __restrict__ T, const float* __restrict__ g,
    const float* __restrict__ b, const float* __restrict__ pos,
    float* __restrict__ H, uint32_t* __restrict__ Hh, uint32_t* __restrict__ Hl)
{
    int warp = threadIdx.x >> 5, lane = threadIdx.x & 31;
    int row = blockIdx.x*8 + warp;
    const float* tr = T + (size_t)row*256;
    float2 v[4]; float s = 0.f, q = 0.f;
    #pragma unroll
    for (int i = 0; i < 4; i++) {
        v[i] = *(const float2*)&tr[2*(i*32 + lane)];
        s += v[i].x + v[i].y; q += v[i].x*v[i].x + v[i].y*v[i].y;
    }
    #pragma unroll
    for (int o = 16; o; o >>= 1) {
        s += __shfl_xor_sync(~0u, s, o);
        q += __shfl_xor_sync(~0u, q, o);
    }
    float mean = s*(1.f/256.f);
    float var  = q*(1.f/256.f) - mean*mean;
    float istd = rsqrtf(var + 1e-5f);
    int n = row & 511;
    float* hr = H + (size_t)row*256;
    const float* pr = pos + n*256;
    #pragma unroll
    for (int i = 0; i < 4; i++) {
        int p = i*32 + lane, c0 = 2*p;
        float y0 = (v[i].x-mean)*istd*g[c0]   + b[c0]   + pr[c0];
        float y1 = (v[i].y-mean)*istd*g[c0+1] + b[c0+1] + pr[c0+1];
        float2 o; o.x = y0; o.y = y1;
        *(float2*)&hr[c0] = o;
        split_pack(y0, y1, Hh[(size_t)row*128 + p], Hl[(size_t)row*128 + p]);
    }
}

// ---------------- BatchNorm ----------------
__global__ __launch_bounds__(256) void bn_part_k(const float* __restrict__ X, float* __restrict__ part) {
    int c = threadIdx.x;
    int r0 = blockIdx.x * 64;
    float s = 0.f, q = 0.f;
    for (int r = 0; r < 64; r++) {
        float v = X[(size_t)(r0+r)*256 + c];
        s += v; q += v*v;
    }
    part[blockIdx.x*256 + c] = s;
    part[128*256 + blockIdx.x*256 + c] = q;
}

__global__ void bn_fin_k(const float* __restrict__ part, const float* __restrict__ g,
                         const float* __restrict__ b, float* __restrict__ sc) {
    int c = threadIdx.x;
    float s = 0.f, q = 0.f;
    for (int i = 0; i < 128; i++) { s += part[i*256 + c]; q += part[32768 + i*256 + c]; }
    float mean = s*(1.f/8192.f);
    float var  = q*(1.f/8192.f) - mean*mean;
    float istd = rsqrtf(var + 1e-5f);
    float scale = g[c]*istd;
    sc[c] = scale;
    sc[256 + c] = b[c] - mean*scale;
}

template<bool WF32>
__global__ void bn_apply_k(float* __restrict__ X, const float* __restrict__ sc,
                           uint32_t* __restrict__ Xh, uint32_t* __restrict__ Xl) {
    int i = blockIdx.x*256 + threadIdx.x;   // pair index
    float2 v = *(const float2*)&X[(size_t)i*2];
    int c = (i*2) & 255;
    float y0 = v.x*sc[c]   + sc[256+c];
    float y1 = v.y*sc[c+1] + sc[257+c];
    if (WF32) { float2 o; o.x = y0; o.y = y1; *(float2*)&X[(size_t)i*2] = o; }
    split_pack(y0, y1, Xh[i], Xl[i]);
}

// ---------------- block-sparse windowed attention ----------------
__global__ __launch_bounds__(256) void attn_k(const float* __restrict__ QKV,
                                              uint32_t* __restrict__ AOh,
                                              uint32_t* __restrict__ AOl) {
    __shared__ float qs[32][33];
    __shared__ float kv[160][33];
    __shared__ float S[32][160];
    int bid = blockIdx.x;
    int qb = bid & 15, h = (bid >> 4) & 7, b = bid >> 7;
    int t = threadIdx.x;
    const float* base = QKV + (size_t)b*512*768;

    {
        int qr = t >> 3, e = (t & 7)*4;
        float4 v = *(const float4*)&base[(size_t)(qb*32 + qr)*768 + h*32 + e];
        qs[qr][e] = v.x; qs[qr][e+1] = v.y; qs[qr][e+2] = v.z; qs[qr][e+3] = v.w;
    }
    {
        int e = (t & 7)*4;
        for (int j = t >> 3; j < 160; j += 32) {
            int kb = qb + (j >> 5) - 2;
            float4 v = make_float4(0.f,0.f,0.f,0.f);
            if (kb >= 0 && kb < 16)
                v = *(const float4*)&base[(size_t)(kb*32 + (j & 31))*768 + 256 + h*32 + e];
            kv[j][e] = v.x; kv[j][e+1] = v.y; kv[j][e+2] = v.z; kv[j][e+3] = v.w;
        }
    }
    __syncthreads();

    const float scale = 0.17677669529663687f;
    #pragma unroll
    for (int ii = 0; ii < 20; ii++) {
        int idx = t + ii*256;
        int qr = idx/160, j = idx - qr*160;
        int kb = qb + (j >> 5) - 2;
        float a = 0.f;
        #pragma unroll
        for (int k = 0; k < 32; k++) a += qs[qr][k]*kv[j][k];
        S[qr][j] = (kb >= 0 && kb < 16) ? a*scale : -1e9f;
    }
    __syncthreads();

    {
        int warp = t >> 5, lane = t & 31;
        for (int qr = warp; qr < 32; qr += 8) {
            float vv[5]; float m = -1e30f;
            #pragma unroll
            for (int i = 0; i < 5; i++) { vv[i] = S[qr][lane + 32*i]; m = fmaxf(m, vv[i]); }
            #pragma unroll
            for (int o = 16; o; o >>= 1) m = fmaxf(m, __shfl_xor_sync(~0u, m, o));
            float s = 0.f;
            #pragma unroll
            for (int i = 0; i < 5; i++) { vv[i] = expf(vv[i] - m); s += vv[i]; }
            #pragma unroll
            for (int o = 16; o; o >>= 1) s += __shfl_xor_sync(~0u, s, o);
            float inv = 1.f/s;
            #pragma unroll
            for (int i = 0; i < 5; i++) S[qr][lane + 32*i] = vv[i]*inv;
        }
    }
    {
        int e = (t & 7)*4;
        for (int j = t >> 3; j < 160; j += 32) {
            int kb = qb + (j >> 5) - 2;
            float4 v = make_float4(0.f,0.f,0.f,0.f);
            if (kb >= 0 && kb < 16)
                v = *(const float4*)&base[(size_t)(kb*32 + (j & 31))*768 + 512 + h*32 + e];
            kv[j][e] = v.x; kv[j][e+1] = v.y; kv[j][e+2] = v.z; kv[j][e+3] = v.w;
        }
    }
    __syncthreads();

    #pragma unroll
    for (int ii = 0; ii < 2; ii++) {
        int idx = t + ii*256;        // 512 pairs: 32 rows x 16 pairs
        int qr = idx >> 4, ep = idx & 15;
        int e0 = ep*2;
        float a0 = 0.f, a1 = 0.f;
        #pragma unroll 8
        for (int j = 0; j < 160; j++) {
            float p = S[qr][j];
            a0 += p*kv[j][e0];
            a1 += p*kv[j][e0+1];
        }
        size_t pi = (size_t)(b*512 + qb*32 + qr)*128 + h*16 + ep;
        split_pack(a0, a1, AOh[pi], AOl[pi]);
    }
}

// ---------------- fcl ----------------
__global__ __launch_bounds__(128) void fcl_part_k(
    const float* __restrict__ P, const float* __restrict__ W, float* __restrict__ out)
{
    __shared__ float As[16][128];
    int gch = blockIdx.x;
    int j = threadIdx.x;
    float acc[16];
    #pragma unroll
    for (int b = 0; b < 16; b++) acc[b] = 0.f;
    int k0 = gch*2048;
    for (int s = 0; s < 16; s++) {
        int kb = k0 + s*128;
        __syncthreads();
        for (int idx = j; idx < 2048; idx += 128) {
            int b = idx >> 7, kk = idx & 127;
            As[b][kk] = P[(size_t)b*327680 + kb + kk];
        }
        __syncthreads();
        #pragma unroll 4
        for (int kk = 0; kk < 128; kk++) {
            float w = W[(size_t)(kb + kk)*128 + j];
            #pragma unroll
            for (int b = 0; b < 16; b++) acc[b] += As[b][kk]*w;
        }
    }
    #pragma unroll
    for (int b = 0; b < 16; b++) out[(size_t)gch*2048 + b*128 + j] = acc[b];
}

__global__ void fcl_red_k(const float* __restrict__ part, const float* __restrict__ bias,
                          float* __restrict__ add) {
    int idx = blockIdx.x*256 + threadIdx.x;
    int j = idx & 127;
    float s = 0.f;
    for (int gc = 0; gc < 160; gc++) s += part[(size_t)gc*2048 + idx];
    add[idx] = s + bias[j];
}

// ---------------- addbn + heads ----------------
__global__ __launch_bounds__(256) void heads_k(
    const float* __restrict__ add, const float* __restrict__ abg, const float* __restrict__ abb,
    const float* __restrict__ cW1, const float* __restrict__ cb1,
    const float* __restrict__ cW2, const float* __restrict__ cb2,
    const float* __restrict__ bW1, const float* __restrict__ bb1,
    const float* __restrict__ bW2, const float* __restrict__ bb2,
    float* __restrict__ out)
{
    __shared__ float sA[16][128];
    __shared__ float sH[16][256];
    __shared__ float sL[16][45];
    int t = threadIdx.x;
    if (t < 128) {
        float s = 0.f, q = 0.f;
        for (int b = 0; b < 16; b++) { float v = add[b*128 + t]; s += v; q += v*v; }
        float mean = s*(1.f/16.f);
        float var  = q*(1.f/16.f) - mean*mean;
        float istd = rsqrtf(var + 1e-5f);
        float sc = abg[t]*istd, sh = abb[t] - mean*sc;
        for (int b = 0; b < 16; b++) sA[b][t] = add[b*128 + t]*sc + sh;
    }
    __syncthreads();
    for (int idx = t; idx < 4096; idx += 256) {
        int b = idx >> 8, u = idx & 255;
        float a = cb1[u];
        for (int c = 0; c < 128; c++) a += sA[b][c]*cW1[c*256 + u];
        sH[b][u] = fmaxf(a, 0.f);
    }
    __syncthreads();
    for (int idx = t; idx < 720; idx += 256) {
        int b = idx/45, o = idx - b*45;
        float a = cb2[o];
        for (int u = 0; u < 256; u++) a += sH[b][u]*cW2[u*45 + o];
        sL[b][o] = a;
    }
    __syncthreads();
    if (t < 16) {
        int b = t;
        float m = -1e30f;
        for (int o = 0; o < 45; o++) m = fmaxf(m, sL[b][o]);
        float s = 0.f; float e[45];
        for (int o = 0; o < 45; o++) { e[o] = expf(sL[b][o] - m); s += e[o]; }
        float inv = 1.f/s;
        for (int o = 0; o < 45; o++)
            out[b*81 + (o/5)*9 + (o%5)] = e[o]*inv;
    }
    __syncthreads();
    for (int idx = t; idx < 2048; idx += 256) {
        int b = idx >> 7, u = idx & 127;
        float a = bb1[u];
        for (int c = 0; c < 128; c++) a += sA[b][c]*bW1[c*128 + u];
        sH[b][u] = fmaxf(a, 0.f);
    }
    __syncthreads();
    for (int idx = t; idx < 576; idx += 256) {
        int b = idx/36, o = idx - b*36;
        float a = bb2[o];
        for (int u = 0; u < 128; u++) a += sH[b][u]*bW2[u*36 + o];
        out[b*81 + (o/4)*9 + 5 + (o%4)] = a;
    }
}

// ---------------- host ----------------
extern "C" void kernel_launch(void* const* d_in, const int* in_sizes, int n_in,
                              void* d_out, int out_size) {
    const float* x       = (const float*)d_in[0];
    const float* patch_W = (const float*)d_in[1];
    const float* patch_b = (const float*)d_in[2];
    const float* ln_g    = (const float*)d_in[3];
    const float* ln_b    = (const float*)d_in[4];
    const float* ff_W1   = (const float*)d_in[5];
    const float* ff_b1   = (const float*)d_in[6];
    const float* ff_W2   = (const float*)d_in[7];
    const float* ff_b2   = (const float*)d_in[8];
    const float* Wqkv    = (const float*)d_in[9];
    const float* bqkv    = (const float*)d_in[10];
    const float* Wo      = (const float*)d_in[11];
    const float* bo      = (const float*)d_in[12];
    const float* bn1_g   = (const float*)d_in[13];
    const float* bn1_b   = (const float*)d_in[14];
    const float* bn2_g   = (const float*)d_in[15];
    const float* bn2_b   = (const float*)d_in[16];
    const float* pyr_W   = (const float*)d_in[17];
    const float* pyr_b   = (const float*)d_in[18];
    const float* fcl_W   = (const float*)d_in[19];
    const float* fcl_b   = (const float*)d_in[20];
    const float* addbn_g = (const float*)d_in[21];
    const float* addbn_b = (const float*)d_in[22];
    const float* cls_W1  = (const float*)d_in[23];
    const float* cls_b1  = (const float*)d_in[24];
    const float* cls_W2  = (const float*)d_in[25];
    const float* cls_b2  = (const float*)d_in[26];
    const float* box_W1  = (const float*)d_in[27];
    const float* box_b1  = (const float*)d_in[28];
    const float* box_W2  = (const float*)d_in[29];
    const float* box_b2  = (const float*)d_in[30];

    static float *X=nullptr,*T,*H,*QKV,*POS,*BNP,*BNS,*PF,*FP,*ADD;
    static uint32_t *Xh,*Xl,*Hh,*Hl,*Th,*Tl,*Gh,*Gl,*Fh,*Fl,*AOh,*AOl;
    static uint32_t *Wph,*Wpl,*W1h,*W1l,*W2h,*W2l,*Wqh,*Wql,*Woh,*Wol,*Pyh,*Pyl;
    if (!X) {
        cudaGetSymbolAddress((void**)&X,  g_X);
        cudaGetSymbolAddress((void**)&T,  g_T);
        cudaGetSymbolAddress((void**)&H,  g_H);
        cudaGetSymbolAddress((void**)&QKV,g_QKV);
        cudaGetSymbolAddress((void**)&POS,g_POS);
        cudaGetSymbolAddress((void**)&BNP,g_BNP);
        cudaGetSymbolAddress((void**)&BNS,g_BNS);
        cudaGetSymbolAddress((void**)&PF, g_PF);
        cudaGetSymbolAddress((void**)&FP, g_FP);
        cudaGetSymbolAddress((void**)&ADD,g_ADD);
        cudaGetSymbolAddress((void**)&Xh, g_Xh);  cudaGetSymbolAddress((void**)&Xl, g_Xl);
        cudaGetSymbolAddress((void**)&Hh, g_Hh);  cudaGetSymbolAddress((void**)&Hl, g_Hl);
        cudaGetSymbolAddress((void**)&Th, g_Th);  cudaGetSymbolAddress((void**)&Tl, g_Tl);
        cudaGetSymbolAddress((void**)&Gh, g_Gh);  cudaGetSymbolAddress((void**)&Gl, g_Gl);
        cudaGetSymbolAddress((void**)&Fh, g_Fh);  cudaGetSymbolAddress((void**)&Fl, g_Fl);
        cudaGetSymbolAddress((void**)&AOh,g_AOh); cudaGetSymbolAddress((void**)&AOl,g_AOl);
        cudaGetSymbolAddress((void**)&Wph,g_Wph); cudaGetSymbolAddress((void**)&Wpl,g_Wpl);
        cudaGetSymbolAddress((void**)&W1h,g_W1h); cudaGetSymbolAddress((void**)&W1l,g_W1l);
        cudaGetSymbolAddress((void**)&W2h,g_W2h); cudaGetSymbolAddress((void**)&W2l,g_W2l);
        cudaGetSymbolAddress((void**)&Wqh,g_Wqh); cudaGetSymbolAddress((void**)&Wql,g_Wql);
        cudaGetSymbolAddress((void**)&Woh,g_Woh); cudaGetSymbolAddress((void**)&Wol,g_Wol);
        cudaGetSymbolAddress((void**)&Pyh,g_Pyh); cudaGetSymbolAddress((void**)&Pyl,g_Pyl);
    }

    pos_k<<<512,256>>>(POS);
    // weight conversions (fp32 -> bf16 hi/lo [n][k/2])
    wcvt_k<<<128,256>>>(patch_W, Wph, Wpl, 256, 256);
    wcvt_k<<<512,256>>>(ff_W1,   W1h, W1l, 256, 1024);
    wcvt_k<<<512,256>>>(ff_W2,   W2h, W2l, 1024, 256);
    wcvt_k<<<384,256>>>(Wqkv,    Wqh, Wql, 256, 768);
    wcvt_k<<<128,256>>>(Wo,      Woh, Wol, 256, 256);
    for (int l = 0; l < 5; l++)
        wcvt_k<<<64,256>>>(pyr_W + (size_t)l*256*128, Pyh + l*16384, Pyl + l*16384, 256, 128);
    // input conversion
    xcvt_k<<<4096,256>>>(x, Xh, Xl);

    for (int it = 0; it < 5; it++) {
        gemm_bf<E_NONE><<<dim3(2,64),256>>>(Xh, Xl, Wph, Wpl, patch_b, nullptr, T, nullptr, nullptr, MTOK, 256, 256, 0);
        ln_pos_k<<<1024,256>>>(T, ln_g, ln_b, POS, H, Hh, Hl);
        gemm_bf<E_GELU><<<dim3(8,64),256>>>(Hh, Hl, W1h, W1l, ff_b1, nullptr, nullptr, Gh, Gl, MTOK, 1024, 256, 0);
        gemm_bf<E_CVT><<<dim3(2,64),256>>>(Gh, Gl, W2h, W2l, ff_b2, nullptr, nullptr, Fh, Fl, MTOK, 256, 1024, 0);
        gemm_bf<E_NONE><<<dim3(6,64),256>>>(Fh, Fl, Wqh, Wql, bqkv, nullptr, QKV, nullptr, nullptr, MTOK, 768, 256, 0);
        attn_k<<<2048,256>>>(QKV, AOh, AOl);
        gemm_bf<E_ADD><<<dim3(2,64),256>>>(AOh, AOl, Woh, Wol, bo, H, T, nullptr, nullptr, MTOK, 256, 256, 0);
        bn_part_k<<<128,256>>>(T, BNP);
        bn_fin_k<<<1,256>>>(BNP, bn1_g, bn1_b, BNS);
        bn_apply_k<true><<<4096,256>>>(T, BNS, Th, Tl);
        gemm_bf<E_GELU><<<dim3(8,64),256>>>(Th, Tl, W1h, W1l, ff_b1, nullptr, nullptr, Gh, Gl, MTOK, 1024, 256, 0);
        gemm_bf<E_ADD><<<dim3(2,64),256>>>(Gh, Gl, W2h, W2l, ff_b2, T, X, nullptr, nullptr, MTOK, 256, 1024, 0);
        bn_part_k<<<128,256>>>(X, BNP);
        bn_fin_k<<<1,256>>>(BNP, bn2_g, bn2_b, BNS);
        bn_apply_k<false><<<4096,256>>>(X, BNS, Xh, Xl);
        gemm_bf<E_PYR><<<dim3(1,64),256>>>(Xh, Xl, Pyh + it*16384, Pyl + it*16384, pyr_b + it*128,
                                           nullptr, PF, nullptr, nullptr, MTOK, 128, 256, it*65536);
    }

    fcl_part_k<<<160,128>>>(PF, fcl_W, FP);
    fcl_red_k<<<8,256>>>(FP, fcl_b, ADD);
    heads_k<<<1,256>>>(ADD, addbn_g, addbn_b,
                       cls_W1, cls_b1, cls_W2, cls_b2,
                       box_W1, box_b1, box_W2, box_b2,
                       (float*)d_out);
}

// round 5
// speedup vs baseline: 1.8804x; 1.2215x over previous
#include <cuda_runtime.h>
#include <cuda_bf16.h>
#include <math.h>
#include <stdint.h>

// ---------------- sizes ----------------
#define MTOK 8192
#define DMODEL 256
#define HID 1024

// ---------------- fp32 scratch ----------------
__device__ float g_X[MTOK*DMODEL];
__device__ float g_T[MTOK*DMODEL];
__device__ float g_H[MTOK*DMODEL];
__device__ float g_QKV[MTOK*3*DMODEL];
__device__ float g_POS[512*DMODEL];
__device__ float g_BNP[2*128*DMODEL];
__device__ float g_BNS[2*DMODEL];
__device__ float g_PF[16*327680];
__device__ float g_FP[160*16*128];
__device__ float g_ADD[16*128];

// ---------------- bf16 hi/lo packed-pair scratch ([m][k/2] uint32) --------
__device__ uint32_t g_Xh[MTOK*128], g_Xl[MTOK*128];
__device__ uint32_t g_Hh[MTOK*128], g_Hl[MTOK*128];
__device__ uint32_t g_Th[MTOK*128], g_Tl[MTOK*128];
__device__ uint32_t g_Gh[MTOK*512], g_Gl[MTOK*512];
__device__ uint32_t g_Fh[MTOK*128], g_Fl[MTOK*128];
__device__ uint32_t g_AOh[MTOK*128], g_AOl[MTOK*128];
__device__ uint32_t g_Wph[256*128],  g_Wpl[256*128];
__device__ uint32_t g_W1h[1024*128], g_W1l[1024*128];
__device__ uint32_t g_W2h[256*512],  g_W2l[256*512];
__device__ uint32_t g_Wqh[768*128],  g_Wql[768*128];
__device__ uint32_t g_Woh[256*128],  g_Wol[256*128];
__device__ uint32_t g_Pyh[5*128*128], g_Pyl[5*128*128];

// ---------------- helpers ----------------
__device__ __forceinline__ float gelu_tanh(float x) {
    float x3 = x*x*x;
    return 0.5f*x*(1.f + tanhf(0.7978845608028654f*(x + 0.044715f*x3)));
}

__device__ __forceinline__ void split_pack(float v0, float v1, uint32_t& ph, uint32_t& pl) {
    __nv_bfloat16 h0 = __float2bfloat16(v0), h1 = __float2bfloat16(v1);
    float r0 = v0 - __bfloat162float(h0), r1 = v1 - __bfloat162float(h1);
    __nv_bfloat16 l0 = __float2bfloat16(r0), l1 = __float2bfloat16(r1);
    ph = ((uint32_t)__bfloat16_as_ushort(h1) << 16) | (uint32_t)__bfloat16_as_ushort(h0);
    pl = ((uint32_t)__bfloat16_as_ushort(l1) << 16) | (uint32_t)__bfloat16_as_ushort(l0);
}

__device__ __forceinline__ void mma_bf16(float c[4],
    uint32_t a0, uint32_t a1, uint32_t a2, uint32_t a3, uint32_t b0, uint32_t b1)
{
    asm volatile(
        "mma.sync.aligned.m16n8k16.row.col.f32.bf16.bf16.f32 "
        "{%0,%1,%2,%3}, {%4,%5,%6,%7}, {%8,%9}, {%0,%1,%2,%3};\n"
        : "+f"(c[0]), "+f"(c[1]), "+f"(c[2]), "+f"(c[3])
        : "r"(a0), "r"(a1), "r"(a2), "r"(a3), "r"(b0), "r"(b1));
}

__device__ __forceinline__ uint32_t smem_u32(const void* p) {
    uint32_t a;
    asm("{ .reg .u64 t; cvta.to.shared.u64 t, %1; cvt.u32.u64 %0, t; }" : "=r"(a) : "l"(p));
    return a;
}

__device__ __forceinline__ void cp16(uint32_t dst, const void* src) {
    asm volatile("cp.async.cg.shared.global [%0], [%1], 16;" :: "r"(dst), "l"(src));
}

__device__ __forceinline__ void ldsm_x4(uint32_t r[4], uint32_t addr) {
    asm volatile("ldmatrix.sync.aligned.m8n8.x4.shared.b16 {%0,%1,%2,%3}, [%4];"
        : "=r"(r[0]), "=r"(r[1]), "=r"(r[2]), "=r"(r[3]) : "r"(addr));
}

// ---------------- conversion kernels ----------------
__global__ void wcvt_k(const float* __restrict__ W, uint32_t* __restrict__ Wh,
                       uint32_t* __restrict__ Wl, int K, int N) {
    int idx = blockIdx.x*256 + threadIdx.x;
    int KP = K >> 1;
    if (idx >= N*KP) return;
    int n = idx / KP, kp = idx - n*KP;
    float v0 = W[(size_t)(2*kp)*N + n];
    float v1 = W[(size_t)(2*kp+1)*N + n];
    split_pack(v0, v1, Wh[idx], Wl[idx]);
}

__global__ void xcvt_k(const float* __restrict__ X, uint32_t* __restrict__ Xh,
                       uint32_t* __restrict__ Xl) {
    int idx = blockIdx.x*256 + threadIdx.x;
    float2 v = *(const float2*)&X[(size_t)idx*2];
    split_pack(v.x, v.y, Xh[idx], Xl[idx]);
}

// ---------------- positional table ----------------
__global__ void pos_k(float* __restrict__ pos) {
    int idx = blockIdx.x*256 + threadIdx.x;
    if (idx >= 512*256) return;
    int n = idx >> 8, d = idx & 255;
    double ang = (double)n / pow(10000.0, (double)(2*(d>>1)) / 256.0);
    pos[idx] = (float)((d & 1) ? cos(ang) : sin(ang));
}

// ---------------- bf16x3 tensor-core GEMM, cp.async 2-stage + ldmatrix ----
// block 128x128, k-tile 32 (16 pairs), 8 warps (4M x 2N), warp tile 32x64
#define E_NONE 0
#define E_GELU 1
#define E_ADD  2
#define E_PYR  3
#define E_CVT  4

// smem layout (uint32 words): [stage][arr][row][20]
// arr: Ah=0, Al=2560, Bh=5120, Bl=7680; stage stride 10240 words
#define GST_W   10240
#define GARR_B  (2560*4)
#define GSM_BYTES (2*GST_W*4)

template<int EPI>
__global__ __launch_bounds__(256, 2) void gemm_bf(
    const uint32_t* __restrict__ Ahg, const uint32_t* __restrict__ Alg,
    const uint32_t* __restrict__ Bhg, const uint32_t* __restrict__ Blg,
    const float* __restrict__ bias, const float* __restrict__ R,
    float* __restrict__ C, uint32_t* __restrict__ Ch, uint32_t* __restrict__ Cl,
    int M, int Nc, int K, int pyr_base)
{
    extern __shared__ uint32_t smem[];
    uint32_t sbase = smem_u32(smem);

    int t = threadIdx.x;
    int lane = t & 31, warp = t >> 5;
    int g = lane >> 2, tid4 = lane & 3;
    int warpM = (warp & 3) * 32;
    int warpN = (warp >> 2) * 64;
    int bm = blockIdx.y * 128, bn = blockIdx.x * 128;
    int KP = K >> 1;

    // lane-dependent ldmatrix bases
    int rowA = (lane & 7) + ((lane >> 3) & 1) * 8;
    int kpA  = (lane >> 4) * 4;
    uint32_t aBase = sbase + (uint32_t)(((warpM + rowA)*20 + kpA) * 4);
    int rowB = (lane & 7) + (lane >> 4) * 8;
    int kpB  = ((lane >> 3) & 1) * 4;
    uint32_t bBase = sbase + 2u*GARR_B + (uint32_t)(((warpN + rowB)*20 + kpB) * 4);

    // staging indices: 2 chunks per thread per array
    int c0r = t >> 2,        c0k = (t & 3) * 4;
    int c1r = (t + 256) >> 2, c1k = ((t + 256) & 3) * 4;

    float acc[2][8][4];
    #pragma unroll
    for (int i = 0; i < 2; i++)
        #pragma unroll
        for (int j = 0; j < 8; j++)
            #pragma unroll
            for (int r = 0; r < 4; r++) acc[i][j][r] = 0.f;

    int ntile = K >> 5;

    // prefetch stage 0
    {
        uint32_t d0 = sbase + (uint32_t)((c0r*20 + c0k)*4);
        uint32_t d1 = sbase + (uint32_t)((c1r*20 + c1k)*4);
        cp16(d0,            Ahg + (size_t)(bm + c0r)*KP + c0k);
        cp16(d1,            Ahg + (size_t)(bm + c1r)*KP + c1k);
        cp16(d0 + GARR_B,   Alg + (size_t)(bm + c0r)*KP + c0k);
        cp16(d1 + GARR_B,   Alg + (size_t)(bm + c1r)*KP + c1k);
        cp16(d0 + 2*GARR_B, Bhg + (size_t)(bn + c0r)*KP + c0k);
        cp16(d1 + 2*GARR_B, Bhg + (size_t)(bn + c1r)*KP + c1k);
        cp16(d0 + 3*GARR_B, Blg + (size_t)(bn + c0r)*KP + c0k);
        cp16(d1 + 3*GARR_B, Blg + (size_t)(bn + c1r)*KP + c1k);
        asm volatile("cp.async.commit_group;");
    }

    for (int kt = 0; kt < ntile; kt++) {
        if (kt + 1 < ntile) {
            int kp0 = (kt + 1) * 16;
            uint32_t sb = sbase + (uint32_t)(((kt + 1) & 1) * GST_W * 4);
            uint32_t d0 = sb + (uint32_t)((c0r*20 + c0k)*4);
            uint32_t d1 = sb + (uint32_t)((c1r*20 + c1k)*4);
            cp16(d0,            Ahg + (size_t)(bm + c0r)*KP + kp0 + c0k);
            cp16(d1,            Ahg + (size_t)(bm + c1r)*KP + kp0 + c1k);
            cp16(d0 + GARR_B,   Alg + (size_t)(bm + c0r)*KP + kp0 + c0k);
            cp16(d1 + GARR_B,   Alg + (size_t)(bm + c1r)*KP + kp0 + c1k);
            cp16(d0 + 2*GARR_B, Bhg + (size_t)(bn + c0r)*KP + kp0 + c0k);
            cp16(d1 + 2*GARR_B, Bhg + (size_t)(bn + c1r)*KP + kp0 + c1k);
            cp16(d0 + 3*GARR_B, Blg + (size_t)(bn + c0r)*KP + kp0 + c0k);
            cp16(d1 + 3*GARR_B, Blg + (size_t)(bn + c1r)*KP + kp0 + c1k);
            asm volatile("cp.async.commit_group;");
            asm volatile("cp.async.wait_group 1;");
        } else {
            asm volatile("cp.async.wait_group 0;");
        }
        __syncthreads();

        uint32_t soff = (uint32_t)((kt & 1) * GST_W * 4);
        #pragma unroll
        for (int ko = 0; ko < 16; ko += 8) {
            uint32_t ah[2][4], al[2][4];
            #pragma unroll
            for (int mt = 0; mt < 2; mt++) {
                uint32_t aoff = soff + (uint32_t)((mt*16*20 + ko)*4);
                ldsm_x4(ah[mt], aBase + aoff);
                ldsm_x4(al[mt], aBase + aoff + GARR_B);
            }
            #pragma unroll
            for (int gb = 0; gb < 4; gb++) {
                uint32_t boff = soff + (uint32_t)((gb*16*20 + ko)*4);
                uint32_t bh[4], bl[4];
                ldsm_x4(bh, bBase + boff);
                ldsm_x4(bl, bBase + boff + GARR_B);
                #pragma unroll
                for (int half = 0; half < 2; half++) {
                    int nt = gb*2 + half;
                    uint32_t bh0 = bh[half*2], bh1 = bh[half*2+1];
                    uint32_t bl0 = bl[half*2], bl1 = bl[half*2+1];
                    #pragma unroll
                    for (int mt = 0; mt < 2; mt++) {
                        mma_bf16(acc[mt][nt], ah[mt][0], ah[mt][1], ah[mt][2], ah[mt][3], bh0, bh1);
                        mma_bf16(acc[mt][nt], ah[mt][0], ah[mt][1], ah[mt][2], ah[mt][3], bl0, bl1);
                        mma_bf16(acc[mt][nt], al[mt][0], al[mt][1], al[mt][2], al[mt][3], bh0, bh1);
                    }
                }
            }
        }
        __syncthreads();
    }

    int NP = Nc >> 1;
    #pragma unroll
    for (int nt = 0; nt < 8; nt++) {
        int col = bn + warpN + nt*8 + tid4*2;
        float bv0 = bias[col], bv1 = bias[col+1];
        #pragma unroll
        for (int mt = 0; mt < 2; mt++) {
            #pragma unroll
            for (int h = 0; h < 2; h++) {
                int row = bm + warpM + mt*16 + g + h*8;
                float v0 = acc[mt][nt][h*2+0] + bv0;
                float v1 = acc[mt][nt][h*2+1] + bv1;
                if (EPI == E_GELU) { v0 = gelu_tanh(v0); v1 = gelu_tanh(v1); }
                if (EPI == E_ADD) {
                    float2 r = *(const float2*)&R[(size_t)row*Nc + col];
                    v0 += r.x; v1 += r.y;
                }
                if (EPI == E_GELU || EPI == E_CVT) {
                    uint32_t ph, pl;
                    split_pack(v0, v1, ph, pl);
                    size_t pi = (size_t)row*NP + (col >> 1);
                    Ch[pi] = ph; Cl[pi] = pl;
                } else if (EPI == E_PYR) {
                    long b0 = (long)(row >> 9)*327680 + pyr_base + (row & 511);
                    C[b0 + (long)col*512]     = v0;
                    C[b0 + (long)(col+1)*512] = v1;
                } else {
                    float2 o; o.x = v0; o.y = v1;
                    *(float2*)&C[(size_t)row*Nc + col] = o;
                }
            }
        }
    }
}

// ---------------- LayerNorm + pos ----------------
__global__ __launch_bounds__(256) void ln_pos_k(
    const float* __restrict__ T, const float* __restrict__ g,
    const float* __restrict__ b, const float* __restrict__ pos,
    float* __restrict__ H, uint32_t* __restrict__ Hh, uint32_t* __restrict__ Hl)
{
    int warp = threadIdx.x >> 5, lane = threadIdx.x & 31;
    int row = blockIdx.x*8 + warp;
    const float* tr = T + (size_t)row*256;
    float2 v[4]; float s = 0.f, q = 0.f;
    #pragma unroll
    for (int i = 0; i < 4; i++) {
        v[i] = *(const float2*)&tr[2*(i*32 + lane)];
        s += v[i].x + v[i].y; q += v[i].x*v[i].x + v[i].y*v[i].y;
    }
    #pragma unroll
    for (int o = 16; o; o >>= 1) {
        s += __shfl_xor_sync(~0u, s, o);
        q += __shfl_xor_sync(~0u, q, o);
    }
    float mean = s*(1.f/256.f);
    float var  = q*(1.f/256.f) - mean*mean;
    float istd = rsqrtf(var + 1e-5f);
    int n = row & 511;
    float* hr = H + (size_t)row*256;
    const float* pr = pos + n*256;
    #pragma unroll
    for (int i = 0; i < 4; i++) {
        int p = i*32 + lane, c0 = 2*p;
        float y0 = (v[i].x-mean)*istd*g[c0]   + b[c0]   + pr[c0];
        float y1 = (v[i].y-mean)*istd*g[c0+1] + b[c0+1] + pr[c0+1];
        float2 o; o.x = y0; o.y = y1;
        *(float2*)&hr[c0] = o;
        split_pack(y0, y1, Hh[(size_t)row*128 + p], Hl[(size_t)row*128 + p]);
    }
}

// ---------------- BatchNorm ----------------
__global__ __launch_bounds__(256) void bn_part_k(const float* __restrict__ X, float* __restrict__ part) {
    int c = threadIdx.x;
    int r0 = blockIdx.x * 64;
    float s = 0.f, q = 0.f;
    for (int r = 0; r < 64; r++) {
        float v = X[(size_t)(r0+r)*256 + c];
        s += v; q += v*v;
    }
    part[blockIdx.x*256 + c] = s;
    part[128*256 + blockIdx.x*256 + c] = q;
}

__global__ void bn_fin_k(const float* __restrict__ part, const float* __restrict__ g,
                         const float* __restrict__ b, float* __restrict__ sc) {
    int c = threadIdx.x;
    float s = 0.f, q = 0.f;
    for (int i = 0; i < 128; i++) { s += part[i*256 + c]; q += part[32768 + i*256 + c]; }
    float mean = s*(1.f/8192.f);
    float var  = q*(1.f/8192.f) - mean*mean;
    float istd = rsqrtf(var + 1e-5f);
    float scale = g[c]*istd;
    sc[c] = scale;
    sc[256 + c] = b[c] - mean*scale;
}

template<bool WF32>
__global__ void bn_apply_k(float* __restrict__ X, const float* __restrict__ sc,
                           uint32_t* __restrict__ Xh, uint32_t* __restrict__ Xl) {
    int i = blockIdx.x*256 + threadIdx.x;
    float2 v = *(const float2*)&X[(size_t)i*2];
    int c = (i*2) & 255;
    float y0 = v.x*sc[c]   + sc[256+c];
    float y1 = v.y*sc[c+1] + sc[257+c];
    if (WF32) { float2 o; o.x = y0; o.y = y1; *(float2*)&X[(size_t)i*2] = o; }
    split_pack(y0, y1, Xh[i], Xl[i]);
}

// ---------------- block-sparse windowed attention ----------------
__global__ __launch_bounds__(256) void attn_k(const float* __restrict__ QKV,
                                              uint32_t* __restrict__ AOh,
                                              uint32_t* __restrict__ AOl) {
    __shared__ float qs[32][33];
    __shared__ float kv[160][33];
    __shared__ float S[32][160];
    int bid = blockIdx.x;
    int qb = bid & 15, h = (bid >> 4) & 7, b = bid >> 7;
    int t = threadIdx.x;
    const float* base = QKV + (size_t)b*512*768;

    {
        int qr = t >> 3, e = (t & 7)*4;
        float4 v = *(const float4*)&base[(size_t)(qb*32 + qr)*768 + h*32 + e];
        qs[qr][e] = v.x; qs[qr][e+1] = v.y; qs[qr][e+2] = v.z; qs[qr][e+3] = v.w;
    }
    {
        int e = (t & 7)*4;
        for (int j = t >> 3; j < 160; j += 32) {
            int kb = qb + (j >> 5) - 2;
            float4 v = make_float4(0.f,0.f,0.f,0.f);
            if (kb >= 0 && kb < 16)
                v = *(const float4*)&base[(size_t)(kb*32 + (j & 31))*768 + 256 + h*32 + e];
            kv[j][e] = v.x; kv[j][e+1] = v.y; kv[j][e+2] = v.z; kv[j][e+3] = v.w;
        }
    }
    __syncthreads();

    const float scale = 0.17677669529663687f;
    #pragma unroll
    for (int ii = 0; ii < 20; ii++) {
        int idx = t + ii*256;
        int qr = idx/160, j = idx - qr*160;
        int kb = qb + (j >> 5) - 2;
        float a = 0.f;
        #pragma unroll
        for (int k = 0; k < 32; k++) a += qs[qr][k]*kv[j][k];
        S[qr][j] = (kb >= 0 && kb < 16) ? a*scale : -1e9f;
    }
    __syncthreads();

    {
        int warp = t >> 5, lane = t & 31;
        for (int qr = warp; qr < 32; qr += 8) {
            float vv[5]; float m = -1e30f;
            #pragma unroll
            for (int i = 0; i < 5; i++) { vv[i] = S[qr][lane + 32*i]; m = fmaxf(m, vv[i]); }
            #pragma unroll
            for (int o = 16; o; o >>= 1) m = fmaxf(m, __shfl_xor_sync(~0u, m, o));
            float s = 0.f;
            #pragma unroll
            for (int i = 0; i < 5; i++) { vv[i] = expf(vv[i] - m); s += vv[i]; }
            #pragma unroll
            for (int o = 16; o; o >>= 1) s += __shfl_xor_sync(~0u, s, o);
            float inv = 1.f/s;
            #pragma unroll
            for (int i = 0; i < 5; i++) S[qr][lane + 32*i] = vv[i]*inv;
        }
    }
    {
        int e = (t & 7)*4;
        for (int j = t >> 3; j < 160; j += 32) {
            int kb = qb + (j >> 5) - 2;
            float4 v = make_float4(0.f,0.f,0.f,0.f);
            if (kb >= 0 && kb < 16)
                v = *(const float4*)&base[(size_t)(kb*32 + (j & 31))*768 + 512 + h*32 + e];
            kv[j][e] = v.x; kv[j][e+1] = v.y; kv[j][e+2] = v.z; kv[j][e+3] = v.w;
        }
    }
    __syncthreads();

    #pragma unroll
    for (int ii = 0; ii < 2; ii++) {
        int idx = t + ii*256;
        int qr = idx >> 4, ep = idx & 15;
        int e0 = ep*2;
        float a0 = 0.f, a1 = 0.f;
        #pragma unroll 8
        for (int j = 0; j < 160; j++) {
            float p = S[qr][j];
            a0 += p*kv[j][e0];
            a1 += p*kv[j][e0+1];
        }
        size_t pi = (size_t)(b*512 + qb*32 + qr)*128 + h*16 + ep;
        split_pack(a0, a1, AOh[pi], AOl[pi]);
    }
}

// ---------------- fcl ----------------
__global__ __launch_bounds__(128) void fcl_part_k(
    const float* __restrict__ P, const float* __restrict__ W, float* __restrict__ out)
{
    __shared__ float As[16][128];
    int gch = blockIdx.x;
    int j = threadIdx.x;
    float acc[16];
    #pragma unroll
    for (int b = 0; b < 16; b++) acc[b] = 0.f;
    int k0 = gch*2048;
    for (int s = 0; s < 16; s++) {
        int kb = k0 + s*128;
        __syncthreads();
        for (int idx = j; idx < 2048; idx += 128) {
            int b = idx >> 7, kk = idx & 127;
            As[b][kk] = P[(size_t)b*327680 + kb + kk];
        }
        __syncthreads();
        #pragma unroll 4
        for (int kk = 0; kk < 128; kk++) {
            float w = W[(size_t)(kb + kk)*128 + j];
            #pragma unroll
            for (int b = 0; b < 16; b++) acc[b] += As[b][kk]*w;
        }
    }
    #pragma unroll
    for (int b = 0; b < 16; b++) out[(size_t)gch*2048 + b*128 + j] = acc[b];
}

__global__ void fcl_red_k(const float* __restrict__ part, const float* __restrict__ bias,
                          float* __restrict__ add) {
    int idx = blockIdx.x*256 + threadIdx.x;
    int j = idx & 127;
    float s = 0.f;
    for (int gc = 0; gc < 160; gc++) s += part[(size_t)gc*2048 + idx];
    add[idx] = s + bias[j];
}

// ---------------- addbn + heads ----------------
__global__ __launch_bounds__(256) void heads_k(
    const float* __restrict__ add, const float* __restrict__ abg, const float* __restrict__ abb,
    const float* __restrict__ cW1, const float* __restrict__ cb1,
    const float* __restrict__ cW2, const float* __restrict__ cb2,
    const float* __restrict__ bW1, const float* __restrict__ bb1,
    const float* __restrict__ bW2, const float* __restrict__ bb2,
    float* __restrict__ out)
{
    __shared__ float sA[16][128];
    __shared__ float sH[16][256];
    __shared__ float sL[16][45];
    int t = threadIdx.x;
    if (t < 128) {
        float s = 0.f, q = 0.f;
        for (int b = 0; b < 16; b++) { float v = add[b*128 + t]; s += v; q += v*v; }
        float mean = s*(1.f/16.f);
        float var  = q*(1.f/16.f) - mean*mean;
        float istd = rsqrtf(var + 1e-5f);
        float sc = abg[t]*istd, sh = abb[t] - mean*sc;
        for (int b = 0; b < 16; b++) sA[b][t] = add[b*128 + t]*sc + sh;
    }
    __syncthreads();
    for (int idx = t; idx < 4096; idx += 256) {
        int b = idx >> 8, u = idx & 255;
        float a = cb1[u];
        for (int c = 0; c < 128; c++) a += sA[b][c]*cW1[c*256 + u];
        sH[b][u] = fmaxf(a, 0.f);
    }
    __syncthreads();
    for (int idx = t; idx < 720; idx += 256) {
        int b = idx/45, o = idx - b*45;
        float a = cb2[o];
        for (int u = 0; u < 256; u++) a += sH[b][u]*cW2[u*45 + o];
        sL[b][o] = a;
    }
    __syncthreads();
    if (t < 16) {
        int b = t;
        float m = -1e30f;
        for (int o = 0; o < 45; o++) m = fmaxf(m, sL[b][o]);
        float s = 0.f; float e[45];
        for (int o = 0; o < 45; o++) { e[o] = expf(sL[b][o] - m); s += e[o]; }
        float inv = 1.f/s;
        for (int o = 0; o < 45; o++)
            out[b*81 + (o/5)*9 + (o%5)] = e[o]*inv;
    }
    __syncthreads();
    for (int idx = t; idx < 2048; idx += 256) {
        int b = idx >> 7, u = idx & 127;
        float a = bb1[u];
        for (int c = 0; c < 128; c++) a += sA[b][c]*bW1[c*128 + u];
        sH[b][u] = fmaxf(a, 0.f);
    }
    __syncthreads();
    for (int idx = t; idx < 576; idx += 256) {
        int b = idx/36, o = idx - b*36;
        float a = bb2[o];
        for (int u = 0; u < 128; u++) a += sH[b][u]*bW2[u*36 + o];
        out[b*81 + (o/4)*9 + 5 + (o%4)] = a;
    }
}

// ---------------- host ----------------
extern "C" void kernel_launch(void* const* d_in, const int* in_sizes, int n_in,
                              void* d_out, int out_size) {
    const float* x       = (const float*)d_in[0];
    const float* patch_W = (const float*)d_in[1];
    const float* patch_b = (const float*)d_in[2];
    const float* ln_g    = (const float*)d_in[3];
    const float* ln_b    = (const float*)d_in[4];
    const float* ff_W1   = (const float*)d_in[5];
    const float* ff_b1   = (const float*)d_in[6];
    const float* ff_W2   = (const float*)d_in[7];
    const float* ff_b2   = (const float*)d_in[8];
    const float* Wqkv    = (const float*)d_in[9];
    const float* bqkv    = (const float*)d_in[10];
    const float* Wo      = (const float*)d_in[11];
    const float* bo      = (const float*)d_in[12];
    const float* bn1_g   = (const float*)d_in[13];
    const float* bn1_b   = (const float*)d_in[14];
    const float* bn2_g   = (const float*)d_in[15];
    const float* bn2_b   = (const float*)d_in[16];
    const float* pyr_W   = (const float*)d_in[17];
    const float* pyr_b   = (const float*)d_in[18];
    const float* fcl_W   = (const float*)d_in[19];
    const float* fcl_b   = (const float*)d_in[20];
    const float* addbn_g = (const float*)d_in[21];
    const float* addbn_b = (const float*)d_in[22];
    const float* cls_W1  = (const float*)d_in[23];
    const float* cls_b1  = (const float*)d_in[24];
    const float* cls_W2  = (const float*)d_in[25];
    const float* cls_b2  = (const float*)d_in[26];
    const float* box_W1  = (const float*)d_in[27];
    const float* box_b1  = (const float*)d_in[28];
    const float* box_W2  = (const float*)d_in[29];
    const float* box_b2  = (const float*)d_in[30];

    static float *X=nullptr,*T,*H,*QKV,*POS,*BNP,*BNS,*PF,*FP,*ADD;
    static uint32_t *Xh,*Xl,*Hh,*Hl,*Th,*Tl,*Gh,*Gl,*Fh,*Fl,*AOh,*AOl;
    static uint32_t *Wph,*Wpl,*W1h,*W1l,*W2h,*W2l,*Wqh,*Wql,*Woh,*Wol,*Pyh,*Pyl;
    if (!X) {
        cudaGetSymbolAddress((void**)&X,  g_X);
        cudaGetSymbolAddress((void**)&T,  g_T);
        cudaGetSymbolAddress((void**)&H,  g_H);
        cudaGetSymbolAddress((void**)&QKV,g_QKV);
        cudaGetSymbolAddress((void**)&POS,g_POS);
        cudaGetSymbolAddress((void**)&BNP,g_BNP);
        cudaGetSymbolAddress((void**)&BNS,g_BNS);
        cudaGetSymbolAddress((void**)&PF, g_PF);
        cudaGetSymbolAddress((void**)&FP, g_FP);
        cudaGetSymbolAddress((void**)&ADD,g_ADD);
        cudaGetSymbolAddress((void**)&Xh, g_Xh);  cudaGetSymbolAddress((void**)&Xl, g_Xl);
        cudaGetSymbolAddress((void**)&Hh, g_Hh);  cudaGetSymbolAddress((void**)&Hl, g_Hl);
        cudaGetSymbolAddress((void**)&Th, g_Th);  cudaGetSymbolAddress((void**)&Tl, g_Tl);
        cudaGetSymbolAddress((void**)&Gh, g_Gh);  cudaGetSymbolAddress((void**)&Gl, g_Gl);
        cudaGetSymbolAddress((void**)&Fh, g_Fh);  cudaGetSymbolAddress((void**)&Fl, g_Fl);
        cudaGetSymbolAddress((void**)&AOh,g_AOh); cudaGetSymbolAddress((void**)&AOl,g_AOl);
        cudaGetSymbolAddress((void**)&Wph,g_Wph); cudaGetSymbolAddress((void**)&Wpl,g_Wpl);
        cudaGetSymbolAddress((void**)&W1h,g_W1h); cudaGetSymbolAddress((void**)&W1l,g_W1l);
        cudaGetSymbolAddress((void**)&W2h,g_W2h); cudaGetSymbolAddress((void**)&W2l,g_W2l);
        cudaGetSymbolAddress((void**)&Wqh,g_Wqh); cudaGetSymbolAddress((void**)&Wql,g_Wql);
        cudaGetSymbolAddress((void**)&Woh,g_Woh); cudaGetSymbolAddress((void**)&Wol,g_Wol);
        cudaGetSymbolAddress((void**)&Pyh,g_Pyh); cudaGetSymbolAddress((void**)&Pyl,g_Pyl);
        cudaFuncSetAttribute(gemm_bf<E_NONE>, cudaFuncAttributeMaxDynamicSharedMemorySize, GSM_BYTES);
        cudaFuncSetAttribute(gemm_bf<E_GELU>, cudaFuncAttributeMaxDynamicSharedMemorySize, GSM_BYTES);
        cudaFuncSetAttribute(gemm_bf<E_ADD>,  cudaFuncAttributeMaxDynamicSharedMemorySize, GSM_BYTES);
        cudaFuncSetAttribute(gemm_bf<E_PYR>,  cudaFuncAttributeMaxDynamicSharedMemorySize, GSM_BYTES);
        cudaFuncSetAttribute(gemm_bf<E_CVT>,  cudaFuncAttributeMaxDynamicSharedMemorySize, GSM_BYTES);
    }

    pos_k<<<512,256>>>(POS);
    wcvt_k<<<128,256>>>(patch_W, Wph, Wpl, 256, 256);
    wcvt_k<<<512,256>>>(ff_W1,   W1h, W1l, 256, 1024);
    wcvt_k<<<512,256>>>(ff_W2,   W2h, W2l, 1024, 256);
    wcvt_k<<<384,256>>>(Wqkv,    Wqh, Wql, 256, 768);
    wcvt_k<<<128,256>>>(Wo,      Woh, Wol, 256, 256);
    for (int l = 0; l < 5; l++)
        wcvt_k<<<64,256>>>(pyr_W + (size_t)l*256*128, Pyh + l*16384, Pyl + l*16384, 256, 128);
    xcvt_k<<<4096,256>>>(x, Xh, Xl);

    for (int it = 0; it < 5; it++) {
        gemm_bf<E_NONE><<<dim3(2,64),256,GSM_BYTES>>>(Xh, Xl, Wph, Wpl, patch_b, nullptr, T, nullptr, nullptr, MTOK, 256, 256, 0);
        ln_pos_k<<<1024,256>>>(T, ln_g, ln_b, POS, H, Hh, Hl);
        gemm_bf<E_GELU><<<dim3(8,64),256,GSM_BYTES>>>(Hh, Hl, W1h, W1l, ff_b1, nullptr, nullptr, Gh, Gl, MTOK, 1024, 256, 0);
        gemm_bf<E_CVT><<<dim3(2,64),256,GSM_BYTES>>>(Gh, Gl, W2h, W2l, ff_b2, nullptr, nullptr, Fh, Fl, MTOK, 256, 1024, 0);
        gemm_bf<E_NONE><<<dim3(6,64),256,GSM_BYTES>>>(Fh, Fl, Wqh, Wql, bqkv, nullptr, QKV, nullptr, nullptr, MTOK, 768, 256, 0);
        attn_k<<<2048,256>>>(QKV, AOh, AOl);
        gemm_bf<E_ADD><<<dim3(2,64),256,GSM_BYTES>>>(AOh, AOl, Woh, Wol, bo, H, T, nullptr, nullptr, MTOK, 256, 256, 0);
        bn_part_k<<<128,256>>>(T, BNP);
        bn_fin_k<<<1,256>>>(BNP, bn1_g, bn1_b, BNS);
        bn_apply_k<true><<<4096,256>>>(T, BNS, Th, Tl);
        gemm_bf<E_GELU><<<dim3(8,64),256,GSM_BYTES>>>(Th, Tl, W1h, W1l, ff_b1, nullptr, nullptr, Gh, Gl, MTOK, 1024, 256, 0);
        gemm_bf<E_ADD><<<dim3(2,64),256,GSM_BYTES>>>(Gh, Gl, W2h, W2l, ff_b2, T, X, nullptr, nullptr, MTOK, 256, 1024, 0);
        bn_part_k<<<128,256>>>(X, BNP);
        bn_fin_k<<<1,256>>>(BNP, bn2_g, bn2_b, BNS);
        bn_apply_k<false><<<4096,256>>>(X, BNS, Xh, Xl);
        gemm_bf<E_PYR><<<dim3(1,64),256,GSM_BYTES>>>(Xh, Xl, Pyh + it*16384, Pyl + it*16384, pyr_b + it*128,
                                                     nullptr, PF, nullptr, nullptr, MTOK, 128, 256, it*65536);
    }

    fcl_part_k<<<160,128>>>(PF, fcl_W, FP);
    fcl_red_k<<<8,256>>>(FP, fcl_b, ADD);
    heads_k<<<1,256>>>(ADD, addbn_g, addbn_b,
                       cls_W1, cls_b1, cls_W2, cls_b2,
                       box_W1, box_b1, box_W2, box_b2,
                       (float*)d_out);
}

// round 6
// speedup vs baseline: 2.1034x; 1.1186x over previous
#include <cuda_runtime.h>
#include <cuda_bf16.h>
#include <math.h>
#include <stdint.h>

// ---------------- sizes ----------------
#define MTOK 8192
#define DMODEL 256
#define HID 1024

// ---------------- fp32 scratch ----------------
__device__ float g_X[MTOK*DMODEL];
__device__ float g_T[MTOK*DMODEL];
__device__ float g_H[MTOK*DMODEL];
__device__ float g_QKV[MTOK*3*DMODEL];
__device__ float g_POS[512*DMODEL];
__device__ float g_BNP[2*64*DMODEL];    // 64 row-band partials x 256 cols (sum, sumsq)
__device__ float g_BNS[2*DMODEL];
__device__ float g_PF[16*327680];
__device__ float g_FP[640*16*128];      // fcl partials (640 chunks)
__device__ float g_ADD[16*128];

// ---------------- bf16 hi/lo packed-pair scratch ([m][k/2] uint32) --------
__device__ uint32_t g_Xh[MTOK*128], g_Xl[MTOK*128];
__device__ uint32_t g_Hh[MTOK*128], g_Hl[MTOK*128];
__device__ uint32_t g_Th[MTOK*128], g_Tl[MTOK*128];
__device__ uint32_t g_Gh[MTOK*512], g_Gl[MTOK*512];
__device__ uint32_t g_Fh[MTOK*128], g_Fl[MTOK*128];
__device__ uint32_t g_AOh[MTOK*128], g_AOl[MTOK*128];
__device__ uint32_t g_Wph[256*128],  g_Wpl[256*128];
__device__ uint32_t g_W1h[1024*128], g_W1l[1024*128];
__device__ uint32_t g_W2h[256*512],  g_W2l[256*512];
__device__ uint32_t g_Wqh[768*128],  g_Wql[768*128];
__device__ uint32_t g_Woh[256*128],  g_Wol[256*128];
__device__ uint32_t g_Pyh[5*128*128], g_Pyl[5*128*128];

// ---------------- helpers ----------------
__device__ __forceinline__ float gelu_tanh(float x) {
    float x3 = x*x*x;
    return 0.5f*x*(1.f + tanhf(0.7978845608028654f*(x + 0.044715f*x3)));
}

__device__ __forceinline__ void split_pack(float v0, float v1, uint32_t& ph, uint32_t& pl) {
    __nv_bfloat16 h0 = __float2bfloat16(v0), h1 = __float2bfloat16(v1);
    float r0 = v0 - __bfloat162float(h0), r1 = v1 - __bfloat162float(h1);
    __nv_bfloat16 l0 = __float2bfloat16(r0), l1 = __float2bfloat16(r1);
    ph = ((uint32_t)__bfloat16_as_ushort(h1) << 16) | (uint32_t)__bfloat16_as_ushort(h0);
    pl = ((uint32_t)__bfloat16_as_ushort(l1) << 16) | (uint32_t)__bfloat16_as_ushort(l0);
}

__device__ __forceinline__ void mma_bf16(float c[4],
    uint32_t a0, uint32_t a1, uint32_t a2, uint32_t a3, uint32_t b0, uint32_t b1)
{
    asm volatile(
        "mma.sync.aligned.m16n8k16.row.col.f32.bf16.bf16.f32 "
        "{%0,%1,%2,%3}, {%4,%5,%6,%7}, {%8,%9}, {%0,%1,%2,%3};\n"
        : "+f"(c[0]), "+f"(c[1]), "+f"(c[2]), "+f"(c[3])
        : "r"(a0), "r"(a1), "r"(a2), "r"(a3), "r"(b0), "r"(b1));
}

__device__ __forceinline__ uint32_t smem_u32(const void* p) {
    uint32_t a;
    asm("{ .reg .u64 t; cvta.to.shared.u64 t, %1; cvt.u32.u64 %0, t; }" : "=r"(a) : "l"(p));
    return a;
}

__device__ __forceinline__ void cp16(uint32_t dst, const void* src) {
    asm volatile("cp.async.cg.shared.global [%0], [%1], 16;" :: "r"(dst), "l"(src));
}

__device__ __forceinline__ void ldsm_x4(uint32_t r[4], uint32_t addr) {
    asm volatile("ldmatrix.sync.aligned.m8n8.x4.shared.b16 {%0,%1,%2,%3}, [%4];"
        : "=r"(r[0]), "=r"(r[1]), "=r"(r[2]), "=r"(r[3]) : "r"(addr));
}

// ---------------- one-shot weight conversion (all weights) ----------------
// segments (pair counts): patch 32768 | ff1 131072 | ff2 131072 | qkv 98304 | wo 32768 | pyr 81920
__global__ void wcvt_all(
    const float* __restrict__ pW, const float* __restrict__ w1, const float* __restrict__ w2,
    const float* __restrict__ wq, const float* __restrict__ wo, const float* __restrict__ py,
    uint32_t* __restrict__ Wph, uint32_t* __restrict__ Wpl,
    uint32_t* __restrict__ W1h, uint32_t* __restrict__ W1l,
    uint32_t* __restrict__ W2h, uint32_t* __restrict__ W2l,
    uint32_t* __restrict__ Wqh, uint32_t* __restrict__ Wql,
    uint32_t* __restrict__ Woh, uint32_t* __restrict__ Wol,
    uint32_t* __restrict__ Pyh, uint32_t* __restrict__ Pyl)
{
    int idx = blockIdx.x*256 + threadIdx.x;
    const float* src; uint32_t *dh, *dl; int KP, N, li;
    if (idx < 32768)       { src = pW; dh = Wph; dl = Wpl; KP = 128; N = 256; li = idx; }
    else if (idx < 163840) { src = w1; dh = W1h; dl = W1l; KP = 128; N = 1024; li = idx - 32768; }
    else if (idx < 294912) { src = w2; dh = W2h; dl = W2l; KP = 512; N = 256; li = idx - 163840; }
    else if (idx < 393216) { src = wq; dh = Wqh; dl = Wql; KP = 128; N = 768; li = idx - 294912; }
    else if (idx < 425984) { src = wo; dh = Woh; dl = Wol; KP = 128; N = 256; li = idx - 393216; }
    else if (idx < 507904) {
        int r = idx - 425984;
        int l = r >> 14, rem = r & 16383;
        src = py + (size_t)l*32768; dh = Pyh + l*16384; dl = Pyl + l*16384;
        KP = 128; N = 128; li = rem;
    } else return;
    int n = li / KP, kp = li - n*KP;
    float v0 = src[(size_t)(2*kp)*N + n];
    float v1 = src[(size_t)(2*kp+1)*N + n];
    split_pack(v0, v1, dh[li], dl[li]);
}

__global__ void xcvt_k(const float* __restrict__ X, uint32_t* __restrict__ Xh,
                       uint32_t* __restrict__ Xl) {
    int idx = blockIdx.x*256 + threadIdx.x;
    float2 v = *(const float2*)&X[(size_t)idx*2];
    split_pack(v.x, v.y, Xh[idx], Xl[idx]);
}

// ---------------- positional table ----------------
__global__ void pos_k(float* __restrict__ pos) {
    int idx = blockIdx.x*256 + threadIdx.x;
    if (idx >= 512*256) return;
    int n = idx >> 8, d = idx & 255;
    double ang = (double)n / pow(10000.0, (double)(2*(d>>1)) / 256.0);
    pos[idx] = (float)((d & 1) ? cos(ang) : sin(ang));
}

// ---------------- bf16x3 tensor-core GEMM, cp.async 2-stage + ldmatrix ----
#define E_NONE 0
#define E_GELU 1
#define E_ADD  2   // + residual, fp32 out, emits BN column partial stats
#define E_PYR  3
#define E_CVT  4

#define GST_W   10240
#define GARR_B  (2560*4)
#define GSM_BYTES (2*GST_W*4)

template<int EPI>
__global__ __launch_bounds__(256, 2) void gemm_bf(
    const uint32_t* __restrict__ Ahg, const uint32_t* __restrict__ Alg,
    const uint32_t* __restrict__ Bhg, const uint32_t* __restrict__ Blg,
    const float* __restrict__ bias, const float* __restrict__ R,
    float* __restrict__ C, uint32_t* __restrict__ Ch, uint32_t* __restrict__ Cl,
    float* __restrict__ BNPp, int M, int Nc, int K, int pyr_base)
{
    extern __shared__ uint32_t smem[];
    uint32_t sbase = smem_u32(smem);

    int t = threadIdx.x;
    int lane = t & 31, warp = t >> 5;
    int g = lane >> 2, tid4 = lane & 3;
    int warpM = (warp & 3) * 32;
    int warpN = (warp >> 2) * 64;
    int bm = blockIdx.y * 128, bn = blockIdx.x * 128;
    int KP = K >> 1;

    int rowA = (lane & 7) + ((lane >> 3) & 1) * 8;
    int kpA  = (lane >> 4) * 4;
    uint32_t aBase = sbase + (uint32_t)(((warpM + rowA)*20 + kpA) * 4);
    int rowB = (lane & 7) + (lane >> 4) * 8;
    int kpB  = ((lane >> 3) & 1) * 4;
    uint32_t bBase = sbase + 2u*GARR_B + (uint32_t)(((warpN + rowB)*20 + kpB) * 4);

    int c0r = t >> 2,        c0k = (t & 3) * 4;
    int c1r = (t + 256) >> 2, c1k = ((t + 256) & 3) * 4;

    float acc[2][8][4];
    #pragma unroll
    for (int i = 0; i < 2; i++)
        #pragma unroll
        for (int j = 0; j < 8; j++)
            #pragma unroll
            for (int r = 0; r < 4; r++) acc[i][j][r] = 0.f;

    int ntile = K >> 5;

    {
        uint32_t d0 = sbase + (uint32_t)((c0r*20 + c0k)*4);
        uint32_t d1 = sbase + (uint32_t)((c1r*20 + c1k)*4);
        cp16(d0,            Ahg + (size_t)(bm + c0r)*KP + c0k);
        cp16(d1,            Ahg + (size_t)(bm + c1r)*KP + c1k);
        cp16(d0 + GARR_B,   Alg + (size_t)(bm + c0r)*KP + c0k);
        cp16(d1 + GARR_B,   Alg + (size_t)(bm + c1r)*KP + c1k);
        cp16(d0 + 2*GARR_B, Bhg + (size_t)(bn + c0r)*KP + c0k);
        cp16(d1 + 2*GARR_B, Bhg + (size_t)(bn + c1r)*KP + c1k);
        cp16(d0 + 3*GARR_B, Blg + (size_t)(bn + c0r)*KP + c0k);
        cp16(d1 + 3*GARR_B, Blg + (size_t)(bn + c1r)*KP + c1k);
        asm volatile("cp.async.commit_group;");
    }

    for (int kt = 0; kt < ntile; kt++) {
        if (kt + 1 < ntile) {
            int kp0 = (kt + 1) * 16;
            uint32_t sb = sbase + (uint32_t)(((kt + 1) & 1) * GST_W * 4);
            uint32_t d0 = sb + (uint32_t)((c0r*20 + c0k)*4);
            uint32_t d1 = sb + (uint32_t)((c1r*20 + c1k)*4);
            cp16(d0,            Ahg + (size_t)(bm + c0r)*KP + kp0 + c0k);
            cp16(d1,            Ahg + (size_t)(bm + c1r)*KP + kp0 + c1k);
            cp16(d0 + GARR_B,   Alg + (size_t)(bm + c0r)*KP + kp0 + c0k);
            cp16(d1 + GARR_B,   Alg + (size_t)(bm + c1r)*KP + kp0 + c1k);
            cp16(d0 + 2*GARR_B, Bhg + (size_t)(bn + c0r)*KP + kp0 + c0k);
            cp16(d1 + 2*GARR_B, Bhg + (size_t)(bn + c1r)*KP + kp0 + c1k);
            cp16(d0 + 3*GARR_B, Blg + (size_t)(bn + c0r)*KP + kp0 + c0k);
            cp16(d1 + 3*GARR_B, Blg + (size_t)(bn + c1r)*KP + kp0 + c1k);
            asm volatile("cp.async.commit_group;");
            asm volatile("cp.async.wait_group 1;");
        } else {
            asm volatile("cp.async.wait_group 0;");
        }
        __syncthreads();

        uint32_t soff = (uint32_t)((kt & 1) * GST_W * 4);
        #pragma unroll
        for (int ko = 0; ko < 16; ko += 8) {
            uint32_t ah[2][4], al[2][4];
            #pragma unroll
            for (int mt = 0; mt < 2; mt++) {
                uint32_t aoff = soff + (uint32_t)((mt*16*20 + ko)*4);
                ldsm_x4(ah[mt], aBase + aoff);
                ldsm_x4(al[mt], aBase + aoff + GARR_B);
            }
            #pragma unroll
            for (int gb = 0; gb < 4; gb++) {
                uint32_t boff = soff + (uint32_t)((gb*16*20 + ko)*4);
                uint32_t bh[4], bl[4];
                ldsm_x4(bh, bBase + boff);
                ldsm_x4(bl, bBase + boff + GARR_B);
                #pragma unroll
                for (int half = 0; half < 2; half++) {
                    int nt = gb*2 + half;
                    uint32_t bh0 = bh[half*2], bh1 = bh[half*2+1];
                    uint32_t bl0 = bl[half*2], bl1 = bl[half*2+1];
                    #pragma unroll
                    for (int mt = 0; mt < 2; mt++) {
                        mma_bf16(acc[mt][nt], ah[mt][0], ah[mt][1], ah[mt][2], ah[mt][3], bh0, bh1);
                        mma_bf16(acc[mt][nt], ah[mt][0], ah[mt][1], ah[mt][2], ah[mt][3], bl0, bl1);
                        mma_bf16(acc[mt][nt], al[mt][0], al[mt][1], al[mt][2], al[mt][3], bh0, bh1);
                    }
                }
            }
        }
        __syncthreads();
    }

    float* sred = (float*)smem;   // reuse pipeline smem for BN partial reduce
    int NP = Nc >> 1;
    #pragma unroll
    for (int nt = 0; nt < 8; nt++) {
        int col = bn + warpN + nt*8 + tid4*2;
        float bv0 = bias[col], bv1 = bias[col+1];
        float s0 = 0.f, q0 = 0.f, s1 = 0.f, q1 = 0.f;
        #pragma unroll
        for (int mt = 0; mt < 2; mt++) {
            #pragma unroll
            for (int h = 0; h < 2; h++) {
                int row = bm + warpM + mt*16 + g + h*8;
                float v0 = acc[mt][nt][h*2+0] + bv0;
                float v1 = acc[mt][nt][h*2+1] + bv1;
                if (EPI == E_GELU) { v0 = gelu_tanh(v0); v1 = gelu_tanh(v1); }
                if (EPI == E_ADD) {
                    float2 r = *(const float2*)&R[(size_t)row*Nc + col];
                    v0 += r.x; v1 += r.y;
                    s0 += v0; q0 += v0*v0; s1 += v1; q1 += v1*v1;
                }
                if (EPI == E_GELU || EPI == E_CVT) {
                    uint32_t ph, pl;
                    split_pack(v0, v1, ph, pl);
                    size_t pi = (size_t)row*NP + (col >> 1);
                    Ch[pi] = ph; Cl[pi] = pl;
                } else if (EPI == E_PYR) {
                    long b0 = (long)(row >> 9)*327680 + pyr_base + (row & 511);
                    C[b0 + (long)col*512]     = v0;
                    C[b0 + (long)(col+1)*512] = v1;
                } else {
                    float2 o; o.x = v0; o.y = v1;
                    *(float2*)&C[(size_t)row*Nc + col] = o;
                }
            }
        }
        if (EPI == E_ADD) {
            #pragma unroll
            for (int o = 4; o <= 16; o <<= 1) {
                s0 += __shfl_xor_sync(~0u, s0, o);
                q0 += __shfl_xor_sync(~0u, q0, o);
                s1 += __shfl_xor_sync(~0u, s1, o);
                q1 += __shfl_xor_sync(~0u, q1, o);
            }
            if (g == 0) {
                int cc = warpN + nt*8 + tid4*2;
                int strip = warp & 3;
                sred[strip*128 + cc]       = s0;
                sred[strip*128 + cc + 1]   = s1;
                sred[512 + strip*128 + cc]     = q0;
                sred[512 + strip*128 + cc + 1] = q1;
            }
        }
    }
    if (EPI == E_ADD) {
        __syncthreads();
        if (t < 128) {
            float s = sred[t] + sred[128 + t] + sred[256 + t] + sred[384 + t];
            BNPp[blockIdx.y*256 + blockIdx.x*128 + t] = s;
        } else if (t < 256) {
            int c = t - 128;
            float q = sred[512 + c] + sred[640 + c] + sred[768 + c] + sred[896 + c];
            BNPp[16384 + blockIdx.y*256 + blockIdx.x*128 + c] = q;
        }
    }
}

// ---------------- LayerNorm + pos ----------------
__global__ __launch_bounds__(256) void ln_pos_k(
    const float* __restrict__ T, const float* __restrict__ g,
    const float* __restrict__ b, const float* __restrict__ pos,
    float* __restrict__ H, uint32_t* __restrict__ Hh, uint32_t* __restrict__ Hl)
{
    int warp = threadIdx.x >> 5, lane = threadIdx.x & 31;
    int row = blockIdx.x*8 + warp;
    const float* tr = T + (size_t)row*256;
    float2 v[4]; float s = 0.f, q = 0.f;
    #pragma unroll
    for (int i = 0; i < 4; i++) {
        v[i] = *(const float2*)&tr[2*(i*32 + lane)];
        s += v[i].x + v[i].y; q += v[i].x*v[i].x + v[i].y*v[i].y;
    }
    #pragma unroll
    for (int o = 16; o; o >>= 1) {
        s += __shfl_xor_sync(~0u, s, o);
        q += __shfl_xor_sync(~0u, q, o);
    }
    float mean = s*(1.f/256.f);
    float var  = q*(1.f/256.f) - mean*mean;
    float istd = rsqrtf(var + 1e-5f);
    int n = row & 511;
    float* hr = H + (size_t)row*256;
    const float* pr = pos + n*256;
    #pragma unroll
    for (int i = 0; i < 4; i++) {
        int p = i*32 + lane, c0 = 2*p;
        float y0 = (v[i].x-mean)*istd*g[c0]   + b[c0]   + pr[c0];
        float y1 = (v[i].y-mean)*istd*g[c0+1] + b[c0+1] + pr[c0+1];
        float2 o; o.x = y0; o.y = y1;
        *(float2*)&hr[c0] = o;
        split_pack(y0, y1, Hh[(size_t)row*128 + p], Hl[(size_t)row*128 + p]);
    }
}

// ---------------- BatchNorm finalize/apply ----------------
__global__ void bn_fin_k(const float* __restrict__ part, const float* __restrict__ g,
                         const float* __restrict__ b, float* __restrict__ sc) {
    int c = threadIdx.x;
    float s = 0.f, q = 0.f;
    for (int i = 0; i < 64; i++) { s += part[i*256 + c]; q += part[16384 + i*256 + c]; }
    float mean = s*(1.f/8192.f);
    float var  = q*(1.f/8192.f) - mean*mean;
    float istd = rsqrtf(var + 1e-5f);
    float scale = g[c]*istd;
    sc[c] = scale;
    sc[256 + c] = b[c] - mean*scale;
}

template<bool WF32>
__global__ void bn_apply_k(float* __restrict__ X, const float* __restrict__ sc,
                           uint32_t* __restrict__ Xh, uint32_t* __restrict__ Xl) {
    int i = blockIdx.x*256 + threadIdx.x;
    float2 v = *(const float2*)&X[(size_t)i*2];
    int c = (i*2) & 255;
    float y0 = v.x*sc[c]   + sc[256+c];
    float y1 = v.y*sc[c+1] + sc[257+c];
    if (WF32) { float2 o; o.x = y0; o.y = y1; *(float2*)&X[(size_t)i*2] = o; }
    split_pack(y0, y1, Xh[i], Xl[i]);
}

// ---------------- block-sparse windowed attention ----------------
__global__ __launch_bounds__(256) void attn_k(const float* __restrict__ QKV,
                                              uint32_t* __restrict__ AOh,
                                              uint32_t* __restrict__ AOl) {
    __shared__ float qs[32][33];
    __shared__ float kv[160][33];
    __shared__ float S[32][160];
    int bid = blockIdx.x;
    int qb = bid & 15, h = (bid >> 4) & 7, b = bid >> 7;
    int t = threadIdx.x;
    const float* base = QKV + (size_t)b*512*768;

    {
        int qr = t >> 3, e = (t & 7)*4;
        float4 v = *(const float4*)&base[(size_t)(qb*32 + qr)*768 + h*32 + e];
        qs[qr][e] = v.x; qs[qr][e+1] = v.y; qs[qr][e+2] = v.z; qs[qr][e+3] = v.w;
    }
    {
        int e = (t & 7)*4;
        for (int j = t >> 3; j < 160; j += 32) {
            int kb = qb + (j >> 5) - 2;
            float4 v = make_float4(0.f,0.f,0.f,0.f);
            if (kb >= 0 && kb < 16)
                v = *(const float4*)&base[(size_t)(kb*32 + (j & 31))*768 + 256 + h*32 + e];
            kv[j][e] = v.x; kv[j][e+1] = v.y; kv[j][e+2] = v.z; kv[j][e+3] = v.w;
        }
    }
    __syncthreads();

    const float scale = 0.17677669529663687f;
    #pragma unroll
    for (int ii = 0; ii < 20; ii++) {
        int idx = t + ii*256;
        int qr = idx/160, j = idx - qr*160;
        int kb = qb + (j >> 5) - 2;
        float a = 0.f;
        #pragma unroll
        for (int k = 0; k < 32; k++) a += qs[qr][k]*kv[j][k];
        S[qr][j] = (kb >= 0 && kb < 16) ? a*scale : -1e9f;
    }
    __syncthreads();

    {
        int warp = t >> 5, lane = t & 31;
        for (int qr = warp; qr < 32; qr += 8) {
            float vv[5]; float m = -1e30f;
            #pragma unroll
            for (int i = 0; i < 5; i++) { vv[i] = S[qr][lane + 32*i]; m = fmaxf(m, vv[i]); }
            #pragma unroll
            for (int o = 16; o; o >>= 1) m = fmaxf(m, __shfl_xor_sync(~0u, m, o));
            float s = 0.f;
            #pragma unroll
            for (int i = 0; i < 5; i++) { vv[i] = expf(vv[i] - m); s += vv[i]; }
            #pragma unroll
            for (int o = 16; o; o >>= 1) s += __shfl_xor_sync(~0u, s, o);
            float inv = 1.f/s;
            #pragma unroll
            for (int i = 0; i < 5; i++) S[qr][lane + 32*i] = vv[i]*inv;
        }
    }
    {
        int e = (t & 7)*4;
        for (int j = t >> 3; j < 160; j += 32) {
            int kb = qb + (j >> 5) - 2;
            float4 v = make_float4(0.f,0.f,0.f,0.f);
            if (kb >= 0 && kb < 16)
                v = *(const float4*)&base[(size_t)(kb*32 + (j & 31))*768 + 512 + h*32 + e];
            kv[j][e] = v.x; kv[j][e+1] = v.y; kv[j][e+2] = v.z; kv[j][e+3] = v.w;
        }
    }
    __syncthreads();

    #pragma unroll
    for (int ii = 0; ii < 2; ii++) {
        int idx = t + ii*256;
        int qr = idx >> 4, ep = idx & 15;
        int e0 = ep*2;
        float a0 = 0.f, a1 = 0.f;
        #pragma unroll 8
        for (int j = 0; j < 160; j++) {
            float p = S[qr][j];
            a0 += p*kv[j][e0];
            a1 += p*kv[j][e0+1];
        }
        size_t pi = (size_t)(b*512 + qb*32 + qr)*128 + h*16 + ep;
        split_pack(a0, a1, AOh[pi], AOl[pi]);
    }
}

// ---------------- fcl: [16 x 327680] @ [327680 x 128] ----------------
// 640 chunks of k=512 for parallelism
__global__ __launch_bounds__(128) void fcl_part_k(
    const float* __restrict__ P, const float* __restrict__ W, float* __restrict__ out)
{
    __shared__ float As[16][128];
    int gch = blockIdx.x;
    int j = threadIdx.x;
    float acc[16];
    #pragma unroll
    for (int b = 0; b < 16; b++) acc[b] = 0.f;
    int k0 = gch*512;
    for (int s = 0; s < 4; s++) {
        int kb = k0 + s*128;
        __syncthreads();
        for (int idx = j; idx < 2048; idx += 128) {
            int b = idx >> 7, kk = idx & 127;
            As[b][kk] = P[(size_t)b*327680 + kb + kk];
        }
        __syncthreads();
        #pragma unroll 4
        for (int kk = 0; kk < 128; kk++) {
            float w = W[(size_t)(kb + kk)*128 + j];
            #pragma unroll
            for (int b = 0; b < 16; b++) acc[b] += As[b][kk]*w;
        }
    }
    #pragma unroll
    for (int b = 0; b < 16; b++) out[(size_t)gch*2048 + b*128 + j] = acc[b];
}

__global__ void fcl_red_k(const float* __restrict__ part, const float* __restrict__ bias,
                          float* __restrict__ add) {
    int idx = blockIdx.x*256 + threadIdx.x;
    int j = idx & 127;
    float s = 0.f;
    for (int gc = 0; gc < 640; gc++) s += part[(size_t)gc*2048 + idx];
    add[idx] = s + bias[j];
}

// ---------------- addbn + heads ----------------
__global__ __launch_bounds__(256) void heads_k(
    const float* __restrict__ add, const float* __restrict__ abg, const float* __restrict__ abb,
    const float* __restrict__ cW1, const float* __restrict__ cb1,
    const float* __restrict__ cW2, const float* __restrict__ cb2,
    const float* __restrict__ bW1, const float* __restrict__ bb1,
    const float* __restrict__ bW2, const float* __restrict__ bb2,
    float* __restrict__ out)
{
    __shared__ float sA[16][128];
    __shared__ float sH[16][256];
    __shared__ float sL[16][45];
    int t = threadIdx.x;
    if (t < 128) {
        float s = 0.f, q = 0.f;
        for (int b = 0; b < 16; b++) { float v = add[b*128 + t]; s += v; q += v*v; }
        float mean = s*(1.f/16.f);
        float var  = q*(1.f/16.f) - mean*mean;
        float istd = rsqrtf(var + 1e-5f);
        float sc = abg[t]*istd, sh = abb[t] - mean*sc;
        for (int b = 0; b < 16; b++) sA[b][t] = add[b*128 + t]*sc + sh;
    }
    __syncthreads();
    for (int idx = t; idx < 4096; idx += 256) {
        int b = idx >> 8, u = idx & 255;
        float a = cb1[u];
        for (int c = 0; c < 128; c++) a += sA[b][c]*cW1[c*256 + u];
        sH[b][u] = fmaxf(a, 0.f);
    }
    __syncthreads();
    for (int idx = t; idx < 720; idx += 256) {
        int b = idx/45, o = idx - b*45;
        float a = cb2[o];
        for (int u = 0; u < 256; u++) a += sH[b][u]*cW2[u*45 + o];
        sL[b][o] = a;
    }
    __syncthreads();
    if (t < 16) {
        int b = t;
        float m = -1e30f;
        for (int o = 0; o < 45; o++) m = fmaxf(m, sL[b][o]);
        float s = 0.f; float e[45];
        for (int o = 0; o < 45; o++) { e[o] = expf(sL[b][o] - m); s += e[o]; }
        float inv = 1.f/s;
        for (int o = 0; o < 45; o++)
            out[b*81 + (o/5)*9 + (o%5)] = e[o]*inv;
    }
    __syncthreads();
    for (int idx = t; idx < 2048; idx += 256) {
        int b = idx >> 7, u = idx & 127;
        float a = bb1[u];
        for (int c = 0; c < 128; c++) a += sA[b][c]*bW1[c*128 + u];
        sH[b][u] = fmaxf(a, 0.f);
    }
    __syncthreads();
    for (int idx = t; idx < 576; idx += 256) {
        int b = idx/36, o = idx - b*36;
        float a = bb2[o];
        for (int u = 0; u < 128; u++) a += sH[b][u]*bW2[u*36 + o];
        out[b*81 + (o/4)*9 + 5 + (o%4)] = a;
    }
}

// ---------------- host ----------------
extern "C" void kernel_launch(void* const* d_in, const int* in_sizes, int n_in,
                              void* d_out, int out_size) {
    const float* x       = (const float*)d_in[0];
    const float* patch_W = (const float*)d_in[1];
    const float* patch_b = (const float*)d_in[2];
    const float* ln_g    = (const float*)d_in[3];
    const float* ln_b    = (const float*)d_in[4];
    const float* ff_W1   = (const float*)d_in[5];
    const float* ff_b1   = (const float*)d_in[6];
    const float* ff_W2   = (const float*)d_in[7];
    const float* ff_b2   = (const float*)d_in[8];
    const float* Wqkv    = (const float*)d_in[9];
    const float* bqkv    = (const float*)d_in[10];
    const float* Wo      = (const float*)d_in[11];
    const float* bo      = (const float*)d_in[12];
    const float* bn1_g   = (const float*)d_in[13];
    const float* bn1_b   = (const float*)d_in[14];
    const float* bn2_g   = (const float*)d_in[15];
    const float* bn2_b   = (const float*)d_in[16];
    const float* pyr_W   = (const float*)d_in[17];
    const float* pyr_b   = (const float*)d_in[18];
    const float* fcl_W   = (const float*)d_in[19];
    const float* fcl_b   = (const float*)d_in[20];
    const float* addbn_g = (const float*)d_in[21];
    const float* addbn_b = (const float*)d_in[22];
    const float* cls_W1  = (const float*)d_in[23];
    const float* cls_b1  = (const float*)d_in[24];
    const float* cls_W2  = (const float*)d_in[25];
    const float* cls_b2  = (const float*)d_in[26];
    const float* box_W1  = (const float*)d_in[27];
    const float* box_b1  = (const float*)d_in[28];
    const float* box_W2  = (const float*)d_in[29];
    const float* box_b2  = (const float*)d_in[30];

    static float *X=nullptr,*T,*H,*QKV,*POS,*BNP,*BNS,*PF,*FP,*ADD;
    static uint32_t *Xh,*Xl,*Hh,*Hl,*Th,*Tl,*Gh,*Gl,*Fh,*Fl,*AOh,*AOl;
    static uint32_t *Wph,*Wpl,*W1h,*W1l,*W2h,*W2l,*Wqh,*Wql,*Woh,*Wol,*Pyh,*Pyl;
    if (!X) {
        cudaGetSymbolAddress((void**)&X,  g_X);
        cudaGetSymbolAddress((void**)&T,  g_T);
        cudaGetSymbolAddress((void**)&H,  g_H);
        cudaGetSymbolAddress((void**)&QKV,g_QKV);
        cudaGetSymbolAddress((void**)&POS,g_POS);
        cudaGetSymbolAddress((void**)&BNP,g_BNP);
        cudaGetSymbolAddress((void**)&BNS,g_BNS);
        cudaGetSymbolAddress((void**)&PF, g_PF);
        cudaGetSymbolAddress((void**)&FP, g_FP);
        cudaGetSymbolAddress((void**)&ADD,g_ADD);
        cudaGetSymbolAddress((void**)&Xh, g_Xh);  cudaGetSymbolAddress((void**)&Xl, g_Xl);
        cudaGetSymbolAddress((void**)&Hh, g_Hh);  cudaGetSymbolAddress((void**)&Hl, g_Hl);
        cudaGetSymbolAddress((void**)&Th, g_Th);  cudaGetSymbolAddress((void**)&Tl, g_Tl);
        cudaGetSymbolAddress((void**)&Gh, g_Gh);  cudaGetSymbolAddress((void**)&Gl, g_Gl);
        cudaGetSymbolAddress((void**)&Fh, g_Fh);  cudaGetSymbolAddress((void**)&Fl, g_Fl);
        cudaGetSymbolAddress((void**)&AOh,g_AOh); cudaGetSymbolAddress((void**)&AOl,g_AOl);
        cudaGetSymbolAddress((void**)&Wph,g_Wph); cudaGetSymbolAddress((void**)&Wpl,g_Wpl);
        cudaGetSymbolAddress((void**)&W1h,g_W1h); cudaGetSymbolAddress((void**)&W1l,g_W1l);
        cudaGetSymbolAddress((void**)&W2h,g_W2h); cudaGetSymbolAddress((void**)&W2l,g_W2l);
        cudaGetSymbolAddress((void**)&Wqh,g_Wqh); cudaGetSymbolAddress((void**)&Wql,g_Wql);
        cudaGetSymbolAddress((void**)&Woh,g_Woh); cudaGetSymbolAddress((void**)&Wol,g_Wol);
        cudaGetSymbolAddress((void**)&Pyh,g_Pyh); cudaGetSymbolAddress((void**)&Pyl,g_Pyl);
        cudaFuncSetAttribute(gemm_bf<E_NONE>, cudaFuncAttributeMaxDynamicSharedMemorySize, GSM_BYTES);
        cudaFuncSetAttribute(gemm_bf<E_GELU>, cudaFuncAttributeMaxDynamicSharedMemorySize, GSM_BYTES);
        cudaFuncSetAttribute(gemm_bf<E_ADD>,  cudaFuncAttributeMaxDynamicSharedMemorySize, GSM_BYTES);
        cudaFuncSetAttribute(gemm_bf<E_PYR>,  cudaFuncAttributeMaxDynamicSharedMemorySize, GSM_BYTES);
        cudaFuncSetAttribute(gemm_bf<E_CVT>,  cudaFuncAttributeMaxDynamicSharedMemorySize, GSM_BYTES);
    }

    pos_k<<<512,256>>>(POS);                                  // launch 0
    wcvt_all<<<1984,256>>>(patch_W, ff_W1, ff_W2, Wqkv, Wo, pyr_W,
                           Wph, Wpl, W1h, W1l, W2h, W2l,
                           Wqh, Wql, Woh, Wol, Pyh, Pyl);     // launch 1
    xcvt_k<<<4096,256>>>(x, Xh, Xl);                          // launch 2

    for (int it = 0; it < 5; it++) {
        gemm_bf<E_NONE><<<dim3(2,64),256,GSM_BYTES>>>(Xh, Xl, Wph, Wpl, patch_b, nullptr, T, nullptr, nullptr, nullptr, MTOK, 256, 256, 0);
        ln_pos_k<<<1024,256>>>(T, ln_g, ln_b, POS, H, Hh, Hl);
        gemm_bf<E_GELU><<<dim3(8,64),256,GSM_BYTES>>>(Hh, Hl, W1h, W1l, ff_b1, nullptr, nullptr, Gh, Gl, nullptr, MTOK, 1024, 256, 0);
        gemm_bf<E_CVT><<<dim3(2,64),256,GSM_BYTES>>>(Gh, Gl, W2h, W2l, ff_b2, nullptr, nullptr, Fh, Fl, nullptr, MTOK, 256, 1024, 0);
        gemm_bf<E_NONE><<<dim3(6,64),256,GSM_BYTES>>>(Fh, Fl, Wqh, Wql, bqkv, nullptr, QKV, nullptr, nullptr, nullptr, MTOK, 768, 256, 0);
        attn_k<<<2048,256>>>(QKV, AOh, AOl);
        gemm_bf<E_ADD><<<dim3(2,64),256,GSM_BYTES>>>(AOh, AOl, Woh, Wol, bo, H, T, nullptr, nullptr, BNP, MTOK, 256, 256, 0);
        bn_fin_k<<<1,256>>>(BNP, bn1_g, bn1_b, BNS);
        bn_apply_k<true><<<4096,256>>>(T, BNS, Th, Tl);
        gemm_bf<E_GELU><<<dim3(8,64),256,GSM_BYTES>>>(Th, Tl, W1h, W1l, ff_b1, nullptr, nullptr, Gh, Gl, nullptr, MTOK, 1024, 256, 0);
        gemm_bf<E_ADD><<<dim3(2,64),256,GSM_BYTES>>>(Gh, Gl, W2h, W2l, ff_b2, T, X, nullptr, nullptr, BNP, MTOK, 256, 1024, 0);
        bn_fin_k<<<1,256>>>(BNP, bn2_g, bn2_b, BNS);
        bn_apply_k<false><<<4096,256>>>(X, BNS, Xh, Xl);
        gemm_bf<E_PYR><<<dim3(1,64),256,GSM_BYTES>>>(Xh, Xl, Pyh + it*16384, Pyl + it*16384, pyr_b + it*128,
                                                     nullptr, PF, nullptr, nullptr, nullptr, MTOK, 128, 256, it*65536);
    }

    fcl_part_k<<<640,128>>>(PF, fcl_W, FP);
    fcl_red_k<<<8,256>>>(FP, fcl_b, ADD);
    heads_k<<<1,256>>>(ADD, addbn_g, addbn_b,
                       cls_W1, cls_b1, cls_W2, cls_b2,
                       box_W1, box_b1, box_W2, box_b2,
                       (float*)d_out);
}